// round 1
// baseline (speedup 1.0000x reference)
#include <cuda_runtime.h>
#include <math.h>

// Problem constants
constexpr int NB = 4;       // batch
constexpr int NT = 2048;    // seq len
constexpr int NC = 1024;    // channels
constexpr int NH = 16;      // heads
constexpr int ND = 64;      // head dim
constexpr int NM = NB * NT;     // 8192 rows
constexpr int NQKV = 3 * NC;    // 3072

// Scratch (device globals — no runtime allocation)
__device__ float g_q[NB * NH * NT * ND];
__device__ float g_k[NB * NH * NT * ND];
__device__ float g_v[NB * NH * NT * ND];
__device__ float g_y[NB * NH * NT * ND];

// ---------------------------------------------------------------------------
// Kernel 1: QKV GEMM  (x[8192,1024] @ W_attn[1024,3072]) with head-major
// scatter epilogue into g_q/g_k/g_v  [B,H,T,HD]
// BM=128 BN=128 BK=16, 256 threads, 8x8 per thread (strided 16 mapping)
// ---------------------------------------------------------------------------
__global__ __launch_bounds__(256) void gemm_qkv(const float* __restrict__ x,
                                                const float* __restrict__ W) {
    __shared__ float As[16][128];
    __shared__ float Bs[16][128];
    const int bx = blockIdx.x;   // N tile (24)
    const int by = blockIdx.y;   // M tile (64)
    const int tid = threadIdx.x;
    const int tx = tid & 15;
    const int ty = tid >> 4;

    const float* Aptr = x + (size_t)(by * 128) * NC;
    const float* Bptr = W + bx * 128;

    float acc[8][8];
#pragma unroll
    for (int i = 0; i < 8; i++)
#pragma unroll
        for (int j = 0; j < 8; j++) acc[i][j] = 0.0f;

    for (int k0 = 0; k0 < NC; k0 += 16) {
        // load A tile 128x16 (transpose into As[k][m])
#pragma unroll
        for (int t = 0; t < 2; t++) {
            int idx = tid * 2 + t;        // 0..511
            int r = idx >> 2;             // 0..127
            int c4 = (idx & 3) * 4;       // 0,4,8,12
            float4 a = *(const float4*)(Aptr + (size_t)r * NC + k0 + c4);
            As[c4 + 0][r] = a.x; As[c4 + 1][r] = a.y;
            As[c4 + 2][r] = a.z; As[c4 + 3][r] = a.w;
        }
        // load B tile 16x128
#pragma unroll
        for (int t = 0; t < 2; t++) {
            int idx = tid * 2 + t;
            int r = idx >> 5;             // 0..15
            int c4 = (idx & 31) * 4;      // 0..124
            *(float4*)&Bs[r][c4] = *(const float4*)(Bptr + (size_t)(k0 + r) * NQKV + c4);
        }
        __syncthreads();
#pragma unroll
        for (int k = 0; k < 16; k++) {
            float ra[8], rb[8];
#pragma unroll
            for (int i = 0; i < 8; i++) ra[i] = As[k][i * 16 + ty];
#pragma unroll
            for (int j = 0; j < 8; j++) rb[j] = Bs[k][j * 16 + tx];
#pragma unroll
            for (int i = 0; i < 8; i++)
#pragma unroll
                for (int j = 0; j < 8; j++) acc[i][j] += ra[i] * rb[j];
        }
        __syncthreads();
    }

    // epilogue: scatter to head-major q/k/v
#pragma unroll
    for (int i = 0; i < 8; i++) {
        int row = by * 128 + i * 16 + ty;
        int b = row >> 11;          // /2048
        int t = row & 2047;
#pragma unroll
        for (int j = 0; j < 8; j++) {
            int col = bx * 128 + j * 16 + tx;
            int part = col >> 10;
            int c = col & 1023;
            int h = c >> 6;
            int d = c & 63;
            float* dst = (part == 0) ? g_q : (part == 1) ? g_k : g_v;
            dst[(size_t)(((b * NH + h) * NT) + t) * ND + d] = acc[i][j];
        }
    }
}

// ---------------------------------------------------------------------------
// Kernel 2: RoPE in-place on g_q / g_k.  One thread per (row, pair i).
// ---------------------------------------------------------------------------
__global__ void rope_kernel(const int* __restrict__ indices, int which) {
    float* buf = which ? g_k : g_q;
    int gid = blockIdx.x * blockDim.x + threadIdx.x;  // B*H*T*32 threads
    int row = gid >> 5;                // [0, B*H*T)
    int i = gid & 31;                  // pair index, half = 32
    int b = row >> 15;                 // / (H*T = 32768)
    int t = row & (NT - 1);
    int pos = indices[b * NT + t];
    // inv_freq = 10000^(-i/32)
    float inv_freq = expf(-9.210340371976184f * (float)i * (1.0f / 32.0f));
    float ang = (float)pos * inv_freq;
    float sv, cv;
    sincosf(ang, &sv, &cv);
    size_t base = (size_t)row * ND;
    float x1 = buf[base + i];
    float x2 = buf[base + i + 32];
    buf[base + i]      = x1 * cv - x2 * sv;
    buf[base + i + 32] = x1 * sv + x2 * cv;
}

// ---------------------------------------------------------------------------
// Kernel 3: causal flash attention, fp32.
// Block = (b, h, q_tile of 64). 256 threads as 16x16, 4x4 per thread.
// Online softmax with running m, l in shared; O in registers.
// ---------------------------------------------------------------------------
__global__ __launch_bounds__(256) void attn_kernel(const int* __restrict__ indices) {
    const int qt = blockIdx.x;     // 0..31
    const int h = blockIdx.y;
    const int b = blockIdx.z;
    const int q0 = qt * 64;
    const int tid = threadIdx.x;
    const int tx = tid & 15;
    const int ty = tid >> 4;

    extern __shared__ float sm[];
    float* Qs = sm;                     // 64 x 65
    float* Ks = Qs + 64 * 65;
    float* Vs = Ks + 64 * 65;
    float* Ps = Vs + 64 * 65;
    float* m_s = Ps + 64 * 65;          // 64
    float* l_s = m_s + 64;              // 64
    int* qidx = (int*)(l_s + 64);       // 64
    int* kidx = qidx + 64;              // 64

    const size_t head_base = (size_t)((b * NH + h) * NT) * ND;

    // load Q tile + init stats
#pragma unroll
    for (int t = 0; t < 4; t++) {
        int idx = tid + t * 256;       // 0..1023 float4s
        int r = idx >> 4;
        int d4 = (idx & 15) * 4;
        float4 v = *(const float4*)(g_q + head_base + (size_t)(q0 + r) * ND + d4);
        Qs[r * 65 + d4 + 0] = v.x; Qs[r * 65 + d4 + 1] = v.y;
        Qs[r * 65 + d4 + 2] = v.z; Qs[r * 65 + d4 + 3] = v.w;
    }
    if (tid < 64) {
        m_s[tid] = -INFINITY;
        l_s[tid] = 0.0f;
        qidx[tid] = indices[b * NT + q0 + tid];
    }
    __syncthreads();

    float o[4][4];
#pragma unroll
    for (int i = 0; i < 4; i++)
#pragma unroll
        for (int j = 0; j < 4; j++) o[i][j] = 0.0f;

    for (int kt = 0; kt <= qt; kt++) {
        const int k0 = kt * 64;
        // load K, V tiles + kidx
#pragma unroll
        for (int t = 0; t < 4; t++) {
            int idx = tid + t * 256;
            int r = idx >> 4;
            int d4 = (idx & 15) * 4;
            float4 kv = *(const float4*)(g_k + head_base + (size_t)(k0 + r) * ND + d4);
            Ks[r * 65 + d4 + 0] = kv.x; Ks[r * 65 + d4 + 1] = kv.y;
            Ks[r * 65 + d4 + 2] = kv.z; Ks[r * 65 + d4 + 3] = kv.w;
            float4 vv = *(const float4*)(g_v + head_base + (size_t)(k0 + r) * ND + d4);
            Vs[r * 65 + d4 + 0] = vv.x; Vs[r * 65 + d4 + 1] = vv.y;
            Vs[r * 65 + d4 + 2] = vv.z; Vs[r * 65 + d4 + 3] = vv.w;
        }
        if (tid < 64) kidx[tid] = indices[b * NT + k0 + tid];
        __syncthreads();

        // S = scale * Q K^T  (4x4 per thread)
        float s[4][4];
#pragma unroll
        for (int i = 0; i < 4; i++)
#pragma unroll
            for (int j = 0; j < 4; j++) s[i][j] = 0.0f;
#pragma unroll 8
        for (int dd = 0; dd < 64; dd++) {
            float qv[4], kv[4];
#pragma unroll
            for (int i = 0; i < 4; i++) qv[i] = Qs[(ty * 4 + i) * 65 + dd];
#pragma unroll
            for (int j = 0; j < 4; j++) kv[j] = Ks[(tx * 4 + j) * 65 + dd];
#pragma unroll
            for (int i = 0; i < 4; i++)
#pragma unroll
                for (int j = 0; j < 4; j++) s[i][j] += qv[i] * kv[j];
        }
        int qi[4], kj[4];
#pragma unroll
        for (int i = 0; i < 4; i++) qi[i] = qidx[ty * 4 + i];
#pragma unroll
        for (int j = 0; j < 4; j++) kj[j] = kidx[tx * 4 + j];
#pragma unroll
        for (int i = 0; i < 4; i++)
#pragma unroll
            for (int j = 0; j < 4; j++) {
                s[i][j] *= 0.125f;
                if (kj[j] > qi[i]) s[i][j] = -INFINITY;
            }

        // online softmax update
        float alpha[4];
#pragma unroll
        for (int i = 0; i < 4; i++) {
            int r = ty * 4 + i;
            float tm = fmaxf(fmaxf(s[i][0], s[i][1]), fmaxf(s[i][2], s[i][3]));
#pragma unroll
            for (int off = 1; off < 16; off <<= 1)
                tm = fmaxf(tm, __shfl_xor_sync(0xffffffffu, tm, off));
            float mold = m_s[r];
            float newm = fmaxf(mold, tm);
            float rs = 0.0f;
#pragma unroll
            for (int j = 0; j < 4; j++) {
                float p = expf(s[i][j] - newm);
                Ps[r * 65 + tx * 4 + j] = p;
                rs += p;
            }
#pragma unroll
            for (int off = 1; off < 16; off <<= 1)
                rs += __shfl_xor_sync(0xffffffffu, rs, off);
            alpha[i] = expf(mold - newm);
            __syncwarp();
            if (tx == 0) {
                l_s[r] = alpha[i] * l_s[r] + rs;
                m_s[r] = newm;
            }
        }
#pragma unroll
        for (int i = 0; i < 4; i++)
#pragma unroll
            for (int j = 0; j < 4; j++) o[i][j] *= alpha[i];
        __syncthreads();

        // O += P @ V
#pragma unroll 8
        for (int k = 0; k < 64; k++) {
            float pv[4], vv[4];
#pragma unroll
            for (int i = 0; i < 4; i++) pv[i] = Ps[(ty * 4 + i) * 65 + k];
#pragma unroll
            for (int j = 0; j < 4; j++) vv[j] = Vs[k * 65 + tx * 4 + j];
#pragma unroll
            for (int i = 0; i < 4; i++)
#pragma unroll
                for (int j = 0; j < 4; j++) o[i][j] += pv[i] * vv[j];
        }
        __syncthreads();
    }

    // finalize: divide by l, write y head-major
#pragma unroll
    for (int i = 0; i < 4; i++) {
        int r = ty * 4 + i;
        float inv = 1.0f / l_s[r];
#pragma unroll
        for (int j = 0; j < 4; j++) {
            g_y[head_base + (size_t)(q0 + r) * ND + tx * 4 + j] = o[i][j] * inv;
        }
    }
}

// ---------------------------------------------------------------------------
// Kernel 4: output projection  (y[8192,1024] @ W_proj[1024,1024])
// y gathered from head-major g_y.
// ---------------------------------------------------------------------------
__global__ __launch_bounds__(256) void gemm_proj(const float* __restrict__ W,
                                                 float* __restrict__ out) {
    __shared__ float As[16][128];
    __shared__ float Bs[16][128];
    const int bx = blockIdx.x;   // N tile (8)
    const int by = blockIdx.y;   // M tile (64)
    const int tid = threadIdx.x;
    const int tx = tid & 15;
    const int ty = tid >> 4;

    float acc[8][8];
#pragma unroll
    for (int i = 0; i < 8; i++)
#pragma unroll
        for (int j = 0; j < 8; j++) acc[i][j] = 0.0f;

    for (int k0 = 0; k0 < NC; k0 += 16) {
        // load A tile (gather from g_y head-major)
#pragma unroll
        for (int t = 0; t < 2; t++) {
            int idx = tid * 2 + t;
            int r = idx >> 2;             // 0..127 tile row
            int c4 = (idx & 3) * 4;
            int row = by * 128 + r;
            int b = row >> 11;
            int tt = row & 2047;
            int col = k0 + c4;
            int h = col >> 6;
            int d = col & 63;
            float4 a = *(const float4*)(g_y + (size_t)(((b * NH + h) * NT) + tt) * ND + d);
            As[c4 + 0][r] = a.x; As[c4 + 1][r] = a.y;
            As[c4 + 2][r] = a.z; As[c4 + 3][r] = a.w;
        }
#pragma unroll
        for (int t = 0; t < 2; t++) {
            int idx = tid * 2 + t;
            int r = idx >> 5;
            int c4 = (idx & 31) * 4;
            *(float4*)&Bs[r][c4] = *(const float4*)(W + (size_t)(k0 + r) * NC + bx * 128 + c4);
        }
        __syncthreads();
#pragma unroll
        for (int k = 0; k < 16; k++) {
            float ra[8], rb[8];
#pragma unroll
            for (int i = 0; i < 8; i++) ra[i] = As[k][i * 16 + ty];
#pragma unroll
            for (int j = 0; j < 8; j++) rb[j] = Bs[k][j * 16 + tx];
#pragma unroll
            for (int i = 0; i < 8; i++)
#pragma unroll
                for (int j = 0; j < 8; j++) acc[i][j] += ra[i] * rb[j];
        }
        __syncthreads();
    }
#pragma unroll
    for (int i = 0; i < 8; i++) {
        int row = by * 128 + i * 16 + ty;
#pragma unroll
        for (int j = 0; j < 8; j++) {
            int col = bx * 128 + j * 16 + tx;
            out[(size_t)row * NC + col] = acc[i][j];
        }
    }
}

// ---------------------------------------------------------------------------
extern "C" void kernel_launch(void* const* d_in, const int* in_sizes, int n_in,
                              void* d_out, int out_size) {
    const float* x      = (const float*)d_in[0];
    const float* W_attn = (const float*)d_in[1];
    const float* W_proj = (const float*)d_in[2];
    const int*   indices = (const int*)d_in[3];
    float* out = (float*)d_out;

    // attention dynamic smem: 4 tiles of 64x65 + stats + index arrays
    static bool attr_set = false;
    const int attn_smem = (4 * 64 * 65 + 128) * 4 + 128 * 4;
    if (!attr_set) {
        cudaFuncSetAttribute(attn_kernel, cudaFuncAttributeMaxDynamicSharedMemorySize,
                             attn_smem);
        attr_set = true;
    }

    gemm_qkv<<<dim3(NQKV / 128, NM / 128), 256>>>(x, W_attn);

    int rope_threads = NB * NH * NT * 32;   // 4.19M
    rope_kernel<<<rope_threads / 256, 256>>>(indices, 0);
    rope_kernel<<<rope_threads / 256, 256>>>(indices, 1);

    attn_kernel<<<dim3(NT / 64, NH, NB), 256, attn_smem>>>(indices);

    gemm_proj<<<dim3(NC / 128, NM / 128), 256>>>(W_proj, out);
}

// round 3
// speedup vs baseline: 2.7743x; 2.7743x over previous
#include <cuda_runtime.h>
#include <math.h>
#include <stdint.h>

// Problem constants
constexpr int NB = 4;       // batch
constexpr int NT = 2048;    // seq len
constexpr int NC = 1024;    // channels
constexpr int NH = 16;      // heads
constexpr int ND = 64;      // head dim
constexpr int NM = NB * NT;     // 8192 rows
constexpr int NQKV = 3 * NC;    // 3072

// Scratch (device globals — no runtime allocation)
__device__ float g_q[NB * NH * NT * ND];   // [B,H,T,D]
__device__ float g_k[NB * NH * NT * ND];   // [B,H,T,D]
__device__ float g_v[NB * NH * NT * ND];   // [B,H,T,D]
__device__ float g_y[NM * NC];             // [B*T, C]  (proj-friendly)

__device__ __forceinline__ float ftf32(float x) {
    float r;
    asm("cvt.rna.tf32.f32 %0, %1;" : "=f"(r) : "f"(x));
    return r;
}

__device__ __forceinline__ void mma_tf32(float* c, const uint32_t* a, const uint32_t* b) {
    asm volatile(
        "mma.sync.aligned.m16n8k8.row.col.f32.tf32.tf32.f32 "
        "{%0,%1,%2,%3}, {%4,%5,%6,%7}, {%8,%9}, {%0,%1,%2,%3};\n"
        : "+f"(c[0]), "+f"(c[1]), "+f"(c[2]), "+f"(c[3])
        : "r"(a[0]), "r"(a[1]), "r"(a[2]), "r"(a[3]), "r"(b[0]), "r"(b[1]));
}

// ---------------------------------------------------------------------------
// TF32 tensor-core GEMM: C[M,N] = A[M,1024] @ B[1024,N]
// 128x128 tile, BK=16, double-buffered smem, 8 warps (2x4), warp tile 64x32.
// SCATTER=true: epilogue scatters into head-major g_q/g_k/g_v (QKV GEMM).
// ---------------------------------------------------------------------------
template<int N, bool SCATTER>
__global__ __launch_bounds__(256, 2) void gemm_tf32(const float* __restrict__ A,
                                                    const float* __restrict__ B,
                                                    float* __restrict__ C) {
    __shared__ float As[2][16][136];   // [k][m], stride 136 (==8 mod 32 -> conflict-free frags)
    __shared__ float Bs[2][16][136];   // [k][n]
    const int bx = blockIdx.x, by = blockIdx.y;
    const int tid = threadIdx.x;
    const int w = tid >> 5, lane = tid & 31;
    const int qr = lane >> 2, qc = lane & 3;
    const int wm = (w >> 2) * 64, wn = (w & 3) * 32;
    const float* Ap = A + (size_t)(by * 128) * 1024;
    const float* Bp = B + bx * 128;

    float4 pa[2], pb[2];

    auto ldg = [&](int k0) {
#pragma unroll
        for (int t = 0; t < 2; t++) {
            int idx = tid * 2 + t;
            int r = idx >> 2, c4 = (idx & 3) * 4;
            pa[t] = *(const float4*)(Ap + (size_t)r * 1024 + k0 + c4);
            int rb = idx >> 5, cb = (idx & 31) * 4;
            pb[t] = *(const float4*)(Bp + (size_t)(k0 + rb) * N + cb);
        }
    };
    auto sts = [&](int s) {
#pragma unroll
        for (int t = 0; t < 2; t++) {
            int idx = tid * 2 + t;
            int r = idx >> 2, c4 = (idx & 3) * 4;
            As[s][c4 + 0][r] = ftf32(pa[t].x);
            As[s][c4 + 1][r] = ftf32(pa[t].y);
            As[s][c4 + 2][r] = ftf32(pa[t].z);
            As[s][c4 + 3][r] = ftf32(pa[t].w);
            int rb = idx >> 5, cb = (idx & 31) * 4;
            float4 v;
            v.x = ftf32(pb[t].x); v.y = ftf32(pb[t].y);
            v.z = ftf32(pb[t].z); v.w = ftf32(pb[t].w);
            *(float4*)&Bs[s][rb][cb] = v;
        }
    };

    float acc[4][4][4];
#pragma unroll
    for (int i = 0; i < 4; i++)
#pragma unroll
        for (int j = 0; j < 4; j++)
#pragma unroll
            for (int u = 0; u < 4; u++) acc[i][j][u] = 0.0f;

    ldg(0);
    sts(0);
    __syncthreads();
    int s = 0;
    for (int kt = 0; kt < 64; kt++) {
        if (kt < 63) ldg((kt + 1) * 16);
#pragma unroll
        for (int kc = 0; kc < 16; kc += 8) {
            uint32_t af[4][4], bf[4][2];
#pragma unroll
            for (int i = 0; i < 4; i++) {
                af[i][0] = __float_as_uint(As[s][kc + qc][wm + i * 16 + qr]);
                af[i][1] = __float_as_uint(As[s][kc + qc][wm + i * 16 + qr + 8]);
                af[i][2] = __float_as_uint(As[s][kc + qc + 4][wm + i * 16 + qr]);
                af[i][3] = __float_as_uint(As[s][kc + qc + 4][wm + i * 16 + qr + 8]);
            }
#pragma unroll
            for (int j = 0; j < 4; j++) {
                bf[j][0] = __float_as_uint(Bs[s][kc + qc][wn + j * 8 + qr]);
                bf[j][1] = __float_as_uint(Bs[s][kc + 4 + qc][wn + j * 8 + qr]);
            }
#pragma unroll
            for (int i = 0; i < 4; i++)
#pragma unroll
                for (int j = 0; j < 4; j++) mma_tf32(acc[i][j], af[i], bf[j]);
        }
        if (kt < 63) sts(s ^ 1);
        __syncthreads();
        s ^= 1;
    }

    // epilogue
#pragma unroll
    for (int i = 0; i < 4; i++) {
#pragma unroll
        for (int j = 0; j < 4; j++) {
            int r0 = by * 128 + wm + i * 16 + qr;
            int c0 = bx * 128 + wn + j * 8 + 2 * qc;
#pragma unroll
            for (int u = 0; u < 4; u++) {
                int row = r0 + (u >> 1) * 8;
                int col = c0 + (u & 1);
                if (SCATTER) {
                    int b = row >> 11;
                    int t = row & 2047;
                    int part = col >> 10;
                    int c = col & 1023;
                    int h = c >> 6;
                    int d = c & 63;
                    float* dst = (part == 0) ? g_q : (part == 1) ? g_k : g_v;
                    dst[(size_t)(((b * NH + h) * NT) + t) * ND + d] = acc[i][j][u];
                } else {
                    C[(size_t)row * NC + col] = acc[i][j][u];
                }
            }
        }
    }
}

// ---------------------------------------------------------------------------
// RoPE in-place on g_q / g_k.  One thread per (row, pair i).
// ---------------------------------------------------------------------------
__global__ void rope_kernel(const int* __restrict__ indices, int which) {
    float* buf = which ? g_k : g_q;
    int gid = blockIdx.x * blockDim.x + threadIdx.x;
    int row = gid >> 5;                // [0, B*H*T)
    int i = gid & 31;                  // pair index (half = 32)
    int b = row >> 15;                 // / (H*T)
    int t = row & (NT - 1);
    int pos = indices[b * NT + t];
    float inv_freq = expf(-9.210340371976184f * (float)i * (1.0f / 32.0f));
    float ang = (float)pos * inv_freq;
    float sv, cv;
    sincosf(ang, &sv, &cv);
    size_t base = (size_t)row * ND;
    float x1 = buf[base + i];
    float x2 = buf[base + i + 32];
    buf[base + i]      = x1 * cv - x2 * sv;
    buf[base + i + 32] = x1 * sv + x2 * cv;
}

// ---------------------------------------------------------------------------
// Flash attention, TF32 tensor cores.
// Block = (qt of 64, h, b), 128 threads = 4 warps, each warp owns 16 q-rows.
// Online softmax is warp-local (m, l in registers per-thread for 2 rows).
// ---------------------------------------------------------------------------
constexpr int STR = 68;  // smem tile stride (==4 mod 32 -> conflict-free frags)

__global__ __launch_bounds__(128) void attn_kernel(const int* __restrict__ indices) {
    const int qt = blockIdx.x;
    const int h = blockIdx.y;
    const int b = blockIdx.z;
    const int q0 = qt * 64;
    const int tid = threadIdx.x;
    const int w = tid >> 5, lane = tid & 31;
    const int qr = lane >> 2, qc = lane & 3;

    extern __shared__ float sm[];
    float* Qs = sm;                 // [64][STR]  q rows x d  (pre-scaled by 1/8, tf32)
    float* Ks = Qs + 64 * STR;      // [64][STR]  key rows x d (tf32)
    float* Vt = Ks + 64 * STR;      // [64][STR]  d x key  (V transposed, tf32)
    float* Ps = Vt + 64 * STR;      // [64][STR]  q rows x key (tf32 probs)
    int* kidx = (int*)(Ps + 64 * STR);  // [64]

    const size_t head_base = (size_t)((b * NH + h) * NT) * ND;

    // load Q (pre-scaled by softmax scale, tf32-rounded)
#pragma unroll
    for (int t = 0; t < 8; t++) {
        int idx = tid + t * 128;
        int r = idx >> 4, d4 = (idx & 15) * 4;
        float4 v = *(const float4*)(g_q + head_base + (size_t)(q0 + r) * ND + d4);
        Qs[r * STR + d4 + 0] = ftf32(v.x * 0.125f);
        Qs[r * STR + d4 + 1] = ftf32(v.y * 0.125f);
        Qs[r * STR + d4 + 2] = ftf32(v.z * 0.125f);
        Qs[r * STR + d4 + 3] = ftf32(v.w * 0.125f);
    }
    const int qi0 = indices[b * NT + q0 + w * 16 + qr];
    const int qi1 = indices[b * NT + q0 + w * 16 + qr + 8];

    float m0 = -INFINITY, m1 = -INFINITY, l0 = 0.0f, l1 = 0.0f;
    float o[8][4];
#pragma unroll
    for (int j = 0; j < 8; j++)
#pragma unroll
        for (int u = 0; u < 4; u++) o[j][u] = 0.0f;

    for (int kt = 0; kt <= qt; kt++) {
        const int k0 = kt * 64;
        __syncthreads();   // previous iteration's readers done (also covers Q load)
        // load K [key][d], V transposed [d][key], kidx
#pragma unroll
        for (int t = 0; t < 8; t++) {
            int idx = tid + t * 128;
            int r = idx >> 4, d4 = (idx & 15) * 4;
            float4 kv = *(const float4*)(g_k + head_base + (size_t)(k0 + r) * ND + d4);
            Ks[r * STR + d4 + 0] = ftf32(kv.x);
            Ks[r * STR + d4 + 1] = ftf32(kv.y);
            Ks[r * STR + d4 + 2] = ftf32(kv.z);
            Ks[r * STR + d4 + 3] = ftf32(kv.w);
            float4 vv = *(const float4*)(g_v + head_base + (size_t)(k0 + r) * ND + d4);
            Vt[(d4 + 0) * STR + r] = ftf32(vv.x);
            Vt[(d4 + 1) * STR + r] = ftf32(vv.y);
            Vt[(d4 + 2) * STR + r] = ftf32(vv.z);
            Vt[(d4 + 3) * STR + r] = ftf32(vv.w);
        }
        if (tid < 64) kidx[tid] = indices[b * NT + k0 + tid];
        __syncthreads();

        // S = Qs @ Ks^T : per warp 16x64, 8 n-tiles of 8, k over d in 8 chunks
        float s[8][4];
#pragma unroll
        for (int j = 0; j < 8; j++)
#pragma unroll
            for (int u = 0; u < 4; u++) s[j][u] = 0.0f;
#pragma unroll
        for (int kc = 0; kc < 8; kc++) {
            uint32_t af[4];
            af[0] = __float_as_uint(Qs[(w * 16 + qr) * STR + kc * 8 + qc]);
            af[1] = __float_as_uint(Qs[(w * 16 + qr + 8) * STR + kc * 8 + qc]);
            af[2] = __float_as_uint(Qs[(w * 16 + qr) * STR + kc * 8 + qc + 4]);
            af[3] = __float_as_uint(Qs[(w * 16 + qr + 8) * STR + kc * 8 + qc + 4]);
#pragma unroll
            for (int j = 0; j < 8; j++) {
                uint32_t bf[2];
                bf[0] = __float_as_uint(Ks[(j * 8 + qr) * STR + kc * 8 + qc]);
                bf[1] = __float_as_uint(Ks[(j * 8 + qr) * STR + kc * 8 + qc + 4]);
                mma_tf32(s[j], af, bf);
            }
        }

        // causal mask (Q already scaled)
#pragma unroll
        for (int j = 0; j < 8; j++) {
            int c0 = j * 8 + 2 * qc;
            int kd0 = kidx[c0], kd1 = kidx[c0 + 1];
            if (kd0 > qi0) s[j][0] = -INFINITY;
            if (kd1 > qi0) s[j][1] = -INFINITY;
            if (kd0 > qi1) s[j][2] = -INFINITY;
            if (kd1 > qi1) s[j][3] = -INFINITY;
        }

        // online softmax (quad-local rows)
        float tm0 = -INFINITY, tm1 = -INFINITY;
#pragma unroll
        for (int j = 0; j < 8; j++) {
            tm0 = fmaxf(tm0, fmaxf(s[j][0], s[j][1]));
            tm1 = fmaxf(tm1, fmaxf(s[j][2], s[j][3]));
        }
#pragma unroll
        for (int off = 1; off < 4; off <<= 1) {
            tm0 = fmaxf(tm0, __shfl_xor_sync(0xffffffffu, tm0, off));
            tm1 = fmaxf(tm1, __shfl_xor_sync(0xffffffffu, tm1, off));
        }
        float nm0 = fmaxf(m0, tm0), nm1 = fmaxf(m1, tm1);
        float a0 = __expf(m0 - nm0), a1 = __expf(m1 - nm1);
        m0 = nm0; m1 = nm1;
        float rs0 = 0.0f, rs1 = 0.0f;
#pragma unroll
        for (int j = 0; j < 8; j++) {
            s[j][0] = __expf(s[j][0] - nm0);
            s[j][1] = __expf(s[j][1] - nm0);
            s[j][2] = __expf(s[j][2] - nm1);
            s[j][3] = __expf(s[j][3] - nm1);
            rs0 += s[j][0] + s[j][1];
            rs1 += s[j][2] + s[j][3];
        }
#pragma unroll
        for (int off = 1; off < 4; off <<= 1) {
            rs0 += __shfl_xor_sync(0xffffffffu, rs0, off);
            rs1 += __shfl_xor_sync(0xffffffffu, rs1, off);
        }
        l0 = l0 * a0 + rs0;
        l1 = l1 * a1 + rs1;
#pragma unroll
        for (int j = 0; j < 8; j++) {
            o[j][0] *= a0; o[j][1] *= a0;
            o[j][2] *= a1; o[j][3] *= a1;
        }

        // store P (tf32) — warp-local rows, no block sync needed
#pragma unroll
        for (int j = 0; j < 8; j++) {
            float2 p01; p01.x = ftf32(s[j][0]); p01.y = ftf32(s[j][1]);
            float2 p23; p23.x = ftf32(s[j][2]); p23.y = ftf32(s[j][3]);
            *(float2*)&Ps[(w * 16 + qr) * STR + j * 8 + 2 * qc] = p01;
            *(float2*)&Ps[(w * 16 + qr + 8) * STR + j * 8 + 2 * qc] = p23;
        }
        __syncwarp();

        // O += P @ V : k over 64 keys in 8 chunks, 8 d-tiles of 8
#pragma unroll
        for (int kc = 0; kc < 8; kc++) {
            uint32_t af[4];
            af[0] = __float_as_uint(Ps[(w * 16 + qr) * STR + kc * 8 + qc]);
            af[1] = __float_as_uint(Ps[(w * 16 + qr + 8) * STR + kc * 8 + qc]);
            af[2] = __float_as_uint(Ps[(w * 16 + qr) * STR + kc * 8 + qc + 4]);
            af[3] = __float_as_uint(Ps[(w * 16 + qr + 8) * STR + kc * 8 + qc + 4]);
#pragma unroll
            for (int j = 0; j < 8; j++) {
                uint32_t bf[2];
                bf[0] = __float_as_uint(Vt[(j * 8 + qr) * STR + kc * 8 + qc]);
                bf[1] = __float_as_uint(Vt[(j * 8 + qr) * STR + kc * 8 + qc + 4]);
                mma_tf32(o[j], af, bf);
            }
        }
    }

    // finalize: divide by l, write y to [B*T, C] layout
    float inv0 = 1.0f / l0, inv1 = 1.0f / l1;
    size_t out0 = (size_t)(b * NT + q0 + w * 16 + qr) * NC + h * 64;
    size_t out1 = (size_t)(b * NT + q0 + w * 16 + qr + 8) * NC + h * 64;
#pragma unroll
    for (int j = 0; j < 8; j++) {
        int c0 = j * 8 + 2 * qc;
        float2 v0; v0.x = o[j][0] * inv0; v0.y = o[j][1] * inv0;
        float2 v1; v1.x = o[j][2] * inv1; v1.y = o[j][3] * inv1;
        *(float2*)&g_y[out0 + c0] = v0;
        *(float2*)&g_y[out1 + c0] = v1;
    }
}

// ---------------------------------------------------------------------------
extern "C" void kernel_launch(void* const* d_in, const int* in_sizes, int n_in,
                              void* d_out, int out_size) {
    const float* x       = (const float*)d_in[0];
    const float* W_attn  = (const float*)d_in[1];
    const float* W_proj  = (const float*)d_in[2];
    const int*   indices = (const int*)d_in[3];
    float* out = (float*)d_out;

    // One-time setup: attn smem opt-in + REAL device address of g_y.
    // (A __device__ symbol used in host code is NOT a device pointer — that
    //  was the R2 fault. cudaGetSymbolAddress is host-side, alloc-free, and
    //  not a stream op, so it is graph-capture safe.)
    static float* g_y_ptr = nullptr;
    const int attn_smem = (4 * 64 * STR) * 4 + 64 * 4;   // ~69.9 KB
    if (g_y_ptr == nullptr) {
        cudaFuncSetAttribute(attn_kernel, cudaFuncAttributeMaxDynamicSharedMemorySize,
                             attn_smem);
        void* p = nullptr;
        cudaGetSymbolAddress(&p, g_y);
        g_y_ptr = (float*)p;
    }

    gemm_tf32<NQKV, true><<<dim3(NQKV / 128, NM / 128), 256>>>(x, W_attn, nullptr);

    int rope_threads = NB * NH * NT * 32;
    rope_kernel<<<rope_threads / 256, 256>>>(indices, 0);
    rope_kernel<<<rope_threads / 256, 256>>>(indices, 1);

    attn_kernel<<<dim3(NT / 64, NH, NB), 128, attn_smem>>>(indices);

    gemm_tf32<NC, false><<<dim3(NC / 128, NM / 128), 256>>>(g_y_ptr, W_proj, out);
}

// round 4
// speedup vs baseline: 3.0000x; 1.0814x over previous
#include <cuda_runtime.h>
#include <math.h>
#include <stdint.h>

// Problem constants
constexpr int NB = 4;       // batch
constexpr int NT = 2048;    // seq len
constexpr int NC = 1024;    // channels
constexpr int NH = 16;      // heads
constexpr int ND = 64;      // head dim
constexpr int NM = NB * NT;     // 8192 rows
constexpr int NQKV = 3 * NC;    // 3072

// Scratch (device globals — no runtime allocation)
__device__ float g_q[NB * NH * NT * ND];   // [B,H,T,D]
__device__ float g_k[NB * NH * NT * ND];   // [B,H,T,D]
__device__ float g_v[NB * NH * NT * ND];   // [B,H,T,D]
__device__ float g_y[NM * NC];             // [B*T, C]  (proj-friendly)

__device__ __forceinline__ float ftf32(float x) {
    float r;
    asm("cvt.rna.tf32.f32 %0, %1;" : "=f"(r) : "f"(x));
    return r;
}

__device__ __forceinline__ void mma_tf32(float* c, const uint32_t* a, const uint32_t* b) {
    asm volatile(
        "mma.sync.aligned.m16n8k8.row.col.f32.tf32.tf32.f32 "
        "{%0,%1,%2,%3}, {%4,%5,%6,%7}, {%8,%9}, {%0,%1,%2,%3};\n"
        : "+f"(c[0]), "+f"(c[1]), "+f"(c[2]), "+f"(c[3])
        : "r"(a[0]), "r"(a[1]), "r"(a[2]), "r"(a[3]), "r"(b[0]), "r"(b[1]));
}

// ---------------------------------------------------------------------------
// TF32 tensor-core GEMM: C[M,N] = A[M,1024] @ B[1024,N]
// 128x128 tile, BK=16, double-buffered smem, 8 warps (2x4), warp tile 64x32.
// SCATTER=true: epilogue scatters into head-major g_q/g_k/g_v (QKV GEMM).
// ---------------------------------------------------------------------------
template<int N, bool SCATTER>
__global__ __launch_bounds__(256, 2) void gemm_tf32(const float* __restrict__ A,
                                                    const float* __restrict__ B,
                                                    float* __restrict__ C) {
    __shared__ float As[2][16][136];   // [k][m], stride 136 (==8 mod 32 -> conflict-free frags)
    __shared__ float Bs[2][16][136];   // [k][n]
    const int bx = blockIdx.x, by = blockIdx.y;
    const int tid = threadIdx.x;
    const int w = tid >> 5, lane = tid & 31;
    const int qr = lane >> 2, qc = lane & 3;
    const int wm = (w >> 2) * 64, wn = (w & 3) * 32;
    const float* Ap = A + (size_t)(by * 128) * 1024;
    const float* Bp = B + bx * 128;

    float4 pa[2], pb[2];

    auto ldg = [&](int k0) {
#pragma unroll
        for (int t = 0; t < 2; t++) {
            int idx = tid * 2 + t;
            int r = idx >> 2, c4 = (idx & 3) * 4;
            pa[t] = *(const float4*)(Ap + (size_t)r * 1024 + k0 + c4);
            int rb = idx >> 5, cb = (idx & 31) * 4;
            pb[t] = *(const float4*)(Bp + (size_t)(k0 + rb) * N + cb);
        }
    };
    auto sts = [&](int s) {
#pragma unroll
        for (int t = 0; t < 2; t++) {
            int idx = tid * 2 + t;
            int r = idx >> 2, c4 = (idx & 3) * 4;
            As[s][c4 + 0][r] = ftf32(pa[t].x);
            As[s][c4 + 1][r] = ftf32(pa[t].y);
            As[s][c4 + 2][r] = ftf32(pa[t].z);
            As[s][c4 + 3][r] = ftf32(pa[t].w);
            int rb = idx >> 5, cb = (idx & 31) * 4;
            float4 v;
            v.x = ftf32(pb[t].x); v.y = ftf32(pb[t].y);
            v.z = ftf32(pb[t].z); v.w = ftf32(pb[t].w);
            *(float4*)&Bs[s][rb][cb] = v;
        }
    };

    float acc[4][4][4];
#pragma unroll
    for (int i = 0; i < 4; i++)
#pragma unroll
        for (int j = 0; j < 4; j++)
#pragma unroll
            for (int u = 0; u < 4; u++) acc[i][j][u] = 0.0f;

    ldg(0);
    sts(0);
    __syncthreads();
    int s = 0;
    for (int kt = 0; kt < 64; kt++) {
        if (kt < 63) ldg((kt + 1) * 16);
#pragma unroll
        for (int kc = 0; kc < 16; kc += 8) {
            uint32_t af[4][4], bf[4][2];
#pragma unroll
            for (int i = 0; i < 4; i++) {
                af[i][0] = __float_as_uint(As[s][kc + qc][wm + i * 16 + qr]);
                af[i][1] = __float_as_uint(As[s][kc + qc][wm + i * 16 + qr + 8]);
                af[i][2] = __float_as_uint(As[s][kc + qc + 4][wm + i * 16 + qr]);
                af[i][3] = __float_as_uint(As[s][kc + qc + 4][wm + i * 16 + qr + 8]);
            }
#pragma unroll
            for (int j = 0; j < 4; j++) {
                bf[j][0] = __float_as_uint(Bs[s][kc + qc][wn + j * 8 + qr]);
                bf[j][1] = __float_as_uint(Bs[s][kc + 4 + qc][wn + j * 8 + qr]);
            }
#pragma unroll
            for (int i = 0; i < 4; i++)
#pragma unroll
                for (int j = 0; j < 4; j++) mma_tf32(acc[i][j], af[i], bf[j]);
        }
        if (kt < 63) sts(s ^ 1);
        __syncthreads();
        s ^= 1;
    }

    // epilogue
#pragma unroll
    for (int i = 0; i < 4; i++) {
#pragma unroll
        for (int j = 0; j < 4; j++) {
            int r0 = by * 128 + wm + i * 16 + qr;
            int c0 = bx * 128 + wn + j * 8 + 2 * qc;
#pragma unroll
            for (int u = 0; u < 4; u++) {
                int row = r0 + (u >> 1) * 8;
                int col = c0 + (u & 1);
                if (SCATTER) {
                    int b = row >> 11;
                    int t = row & 2047;
                    int part = col >> 10;
                    int c = col & 1023;
                    int h = c >> 6;
                    int d = c & 63;
                    float* dst = (part == 0) ? g_q : (part == 1) ? g_k : g_v;
                    dst[(size_t)(((b * NH + h) * NT) + t) * ND + d] = acc[i][j][u];
                } else {
                    C[(size_t)row * NC + col] = acc[i][j][u];
                }
            }
        }
    }
}

// ---------------------------------------------------------------------------
// RoPE in-place on g_q / g_k.  One thread per (row, pair i).
// ---------------------------------------------------------------------------
__global__ void rope_kernel(const int* __restrict__ indices, int which) {
    float* buf = which ? g_k : g_q;
    int gid = blockIdx.x * blockDim.x + threadIdx.x;
    int row = gid >> 5;                // [0, B*H*T)
    int i = gid & 31;                  // pair index (half = 32)
    int b = row >> 15;                 // / (H*T)
    int t = row & (NT - 1);
    int pos = indices[b * NT + t];
    float inv_freq = expf(-9.210340371976184f * (float)i * (1.0f / 32.0f));
    float ang = (float)pos * inv_freq;
    float sv, cv;
    sincosf(ang, &sv, &cv);
    size_t base = (size_t)row * ND;
    float x1 = buf[base + i];
    float x2 = buf[base + i + 32];
    buf[base + i]      = x1 * cv - x2 * sv;
    buf[base + i + 32] = x1 * sv + x2 * cv;
}

// ---------------------------------------------------------------------------
// Flash attention, TF32 tensor cores.
// Block = (qt of 128, h, b), 128 threads = 4 warps, each warp owns 32 q-rows
// (two m16 MMA tiles). B-fragments are shared across both m-tiles -> 1.5
// LDS words per MMA (was 2.5). Online softmax warp-local.
// ---------------------------------------------------------------------------
constexpr int STR = 68;  // smem tile stride (==4 mod 32 -> conflict-free frags)

__global__ __launch_bounds__(128) void attn_kernel(const int* __restrict__ indices) {
    const int qt = (gridDim.x - 1) - blockIdx.x;   // heavy blocks launch first
    const int h = blockIdx.y;
    const int b = blockIdx.z;
    const int q0 = qt * 128;
    const int tid = threadIdx.x;
    const int w = tid >> 5, lane = tid & 31;
    const int qr = lane >> 2, qc = lane & 3;
    const int rw = w * 32;   // warp's first q-row in tile

    extern __shared__ float sm[];
    float* Qs = sm;                  // [128][STR] q rows x d (pre-scaled, tf32)
    float* Ks = Qs + 128 * STR;      // [64][STR]  key rows x d (tf32)
    float* Vt = Ks + 64 * STR;       // [64][STR]  d x key (V transposed, tf32)
    float* Ps = Vt + 64 * STR;       // [128][STR] q rows x key (tf32 probs)
    int* kidx = (int*)(Ps + 128 * STR);  // [64]

    const size_t head_base = (size_t)((b * NH + h) * NT) * ND;

    // load Q (pre-scaled by softmax scale, tf32-rounded): 128 rows
#pragma unroll
    for (int t = 0; t < 16; t++) {
        int idx = tid + t * 128;       // 0..2047 float4s
        int r = idx >> 4, d4 = (idx & 15) * 4;
        float4 v = *(const float4*)(g_q + head_base + (size_t)(q0 + r) * ND + d4);
        Qs[r * STR + d4 + 0] = ftf32(v.x * 0.125f);
        Qs[r * STR + d4 + 1] = ftf32(v.y * 0.125f);
        Qs[r * STR + d4 + 2] = ftf32(v.z * 0.125f);
        Qs[r * STR + d4 + 3] = ftf32(v.w * 0.125f);
    }
    int qi[4];
#pragma unroll
    for (int mi = 0; mi < 2; mi++) {
        qi[mi * 2 + 0] = indices[b * NT + q0 + rw + mi * 16 + qr];
        qi[mi * 2 + 1] = indices[b * NT + q0 + rw + mi * 16 + qr + 8];
    }

    float mrow[4], lrow[4];
#pragma unroll
    for (int u = 0; u < 4; u++) { mrow[u] = -INFINITY; lrow[u] = 0.0f; }
    float o[2][8][4];
#pragma unroll
    for (int mi = 0; mi < 2; mi++)
#pragma unroll
        for (int j = 0; j < 8; j++)
#pragma unroll
            for (int u = 0; u < 4; u++) o[mi][j][u] = 0.0f;

    const int ktmax = 2 * qt + 1;
    for (int kt = 0; kt <= ktmax; kt++) {
        const int k0 = kt * 64;
        __syncthreads();   // previous iteration's readers done (also covers Q load)
        // load K [key][d], V transposed [d][key], kidx
#pragma unroll
        for (int t = 0; t < 8; t++) {
            int idx = tid + t * 128;
            int r = idx >> 4, d4 = (idx & 15) * 4;
            float4 kv = *(const float4*)(g_k + head_base + (size_t)(k0 + r) * ND + d4);
            Ks[r * STR + d4 + 0] = ftf32(kv.x);
            Ks[r * STR + d4 + 1] = ftf32(kv.y);
            Ks[r * STR + d4 + 2] = ftf32(kv.z);
            Ks[r * STR + d4 + 3] = ftf32(kv.w);
            float4 vv = *(const float4*)(g_v + head_base + (size_t)(k0 + r) * ND + d4);
            Vt[(d4 + 0) * STR + r] = ftf32(vv.x);
            Vt[(d4 + 1) * STR + r] = ftf32(vv.y);
            Vt[(d4 + 2) * STR + r] = ftf32(vv.z);
            Vt[(d4 + 3) * STR + r] = ftf32(vv.w);
        }
        if (tid < 64) kidx[tid] = indices[b * NT + k0 + tid];
        __syncthreads();

        // S = Qs @ Ks^T : per warp 32x64 (2 m-tiles x 8 n-tiles), bf shared
        float s[2][8][4];
#pragma unroll
        for (int mi = 0; mi < 2; mi++)
#pragma unroll
            for (int j = 0; j < 8; j++)
#pragma unroll
                for (int u = 0; u < 4; u++) s[mi][j][u] = 0.0f;
#pragma unroll
        for (int kc = 0; kc < 8; kc++) {
            uint32_t af[2][4];
#pragma unroll
            for (int mi = 0; mi < 2; mi++) {
                int r0 = (rw + mi * 16 + qr) * STR + kc * 8 + qc;
                af[mi][0] = __float_as_uint(Qs[r0]);
                af[mi][1] = __float_as_uint(Qs[r0 + 8 * STR]);
                af[mi][2] = __float_as_uint(Qs[r0 + 4]);
                af[mi][3] = __float_as_uint(Qs[r0 + 8 * STR + 4]);
            }
#pragma unroll
            for (int j = 0; j < 8; j++) {
                uint32_t bf[2];
                bf[0] = __float_as_uint(Ks[(j * 8 + qr) * STR + kc * 8 + qc]);
                bf[1] = __float_as_uint(Ks[(j * 8 + qr) * STR + kc * 8 + qc + 4]);
                mma_tf32(s[0][j], af[0], bf);
                mma_tf32(s[1][j], af[1], bf);
            }
        }

        // mask + online softmax + P store, per m-tile
#pragma unroll
        for (int mi = 0; mi < 2; mi++) {
            float* sj0;
#pragma unroll
            for (int j = 0; j < 8; j++) {
                int c0 = j * 8 + 2 * qc;
                int kd0 = kidx[c0], kd1 = kidx[c0 + 1];
                if (kd0 > qi[mi * 2 + 0]) s[mi][j][0] = -INFINITY;
                if (kd1 > qi[mi * 2 + 0]) s[mi][j][1] = -INFINITY;
                if (kd0 > qi[mi * 2 + 1]) s[mi][j][2] = -INFINITY;
                if (kd1 > qi[mi * 2 + 1]) s[mi][j][3] = -INFINITY;
            }
            float tm0 = -INFINITY, tm1 = -INFINITY;
#pragma unroll
            for (int j = 0; j < 8; j++) {
                tm0 = fmaxf(tm0, fmaxf(s[mi][j][0], s[mi][j][1]));
                tm1 = fmaxf(tm1, fmaxf(s[mi][j][2], s[mi][j][3]));
            }
#pragma unroll
            for (int off = 1; off < 4; off <<= 1) {
                tm0 = fmaxf(tm0, __shfl_xor_sync(0xffffffffu, tm0, off));
                tm1 = fmaxf(tm1, __shfl_xor_sync(0xffffffffu, tm1, off));
            }
            float nm0 = fmaxf(mrow[mi * 2 + 0], tm0);
            float nm1 = fmaxf(mrow[mi * 2 + 1], tm1);
            float a0 = __expf(mrow[mi * 2 + 0] - nm0);
            float a1 = __expf(mrow[mi * 2 + 1] - nm1);
            mrow[mi * 2 + 0] = nm0; mrow[mi * 2 + 1] = nm1;
            float rs0 = 0.0f, rs1 = 0.0f;
#pragma unroll
            for (int j = 0; j < 8; j++) {
                s[mi][j][0] = __expf(s[mi][j][0] - nm0);
                s[mi][j][1] = __expf(s[mi][j][1] - nm0);
                s[mi][j][2] = __expf(s[mi][j][2] - nm1);
                s[mi][j][3] = __expf(s[mi][j][3] - nm1);
                rs0 += s[mi][j][0] + s[mi][j][1];
                rs1 += s[mi][j][2] + s[mi][j][3];
            }
#pragma unroll
            for (int off = 1; off < 4; off <<= 1) {
                rs0 += __shfl_xor_sync(0xffffffffu, rs0, off);
                rs1 += __shfl_xor_sync(0xffffffffu, rs1, off);
            }
            lrow[mi * 2 + 0] = lrow[mi * 2 + 0] * a0 + rs0;
            lrow[mi * 2 + 1] = lrow[mi * 2 + 1] * a1 + rs1;
#pragma unroll
            for (int j = 0; j < 8; j++) {
                o[mi][j][0] *= a0; o[mi][j][1] *= a0;
                o[mi][j][2] *= a1; o[mi][j][3] *= a1;
            }
            // store P (tf32) — warp-local rows
#pragma unroll
            for (int j = 0; j < 8; j++) {
                float2 p01; p01.x = ftf32(s[mi][j][0]); p01.y = ftf32(s[mi][j][1]);
                float2 p23; p23.x = ftf32(s[mi][j][2]); p23.y = ftf32(s[mi][j][3]);
                *(float2*)&Ps[(rw + mi * 16 + qr) * STR + j * 8 + 2 * qc] = p01;
                *(float2*)&Ps[(rw + mi * 16 + qr + 8) * STR + j * 8 + 2 * qc] = p23;
            }
        }
        __syncwarp();

        // O += P @ V : bf shared across both m-tiles
#pragma unroll
        for (int kc = 0; kc < 8; kc++) {
            uint32_t af[2][4];
#pragma unroll
            for (int mi = 0; mi < 2; mi++) {
                int r0 = (rw + mi * 16 + qr) * STR + kc * 8 + qc;
                af[mi][0] = __float_as_uint(Ps[r0]);
                af[mi][1] = __float_as_uint(Ps[r0 + 8 * STR]);
                af[mi][2] = __float_as_uint(Ps[r0 + 4]);
                af[mi][3] = __float_as_uint(Ps[r0 + 8 * STR + 4]);
            }
#pragma unroll
            for (int j = 0; j < 8; j++) {
                uint32_t bf[2];
                bf[0] = __float_as_uint(Vt[(j * 8 + qr) * STR + kc * 8 + qc]);
                bf[1] = __float_as_uint(Vt[(j * 8 + qr) * STR + kc * 8 + qc + 4]);
                mma_tf32(o[0][j], af[0], bf);
                mma_tf32(o[1][j], af[1], bf);
            }
        }
    }

    // finalize: divide by l, write y to [B*T, C] layout
#pragma unroll
    for (int mi = 0; mi < 2; mi++) {
        float inv0 = 1.0f / lrow[mi * 2 + 0];
        float inv1 = 1.0f / lrow[mi * 2 + 1];
        size_t out0 = (size_t)(b * NT + q0 + rw + mi * 16 + qr) * NC + h * 64;
        size_t out1 = (size_t)(b * NT + q0 + rw + mi * 16 + qr + 8) * NC + h * 64;
#pragma unroll
        for (int j = 0; j < 8; j++) {
            int c0 = j * 8 + 2 * qc;
            float2 v0; v0.x = o[mi][j][0] * inv0; v0.y = o[mi][j][1] * inv0;
            float2 v1; v1.x = o[mi][j][2] * inv1; v1.y = o[mi][j][3] * inv1;
            *(float2*)&g_y[out0 + c0] = v0;
            *(float2*)&g_y[out1 + c0] = v1;
        }
    }
}

// ---------------------------------------------------------------------------
extern "C" void kernel_launch(void* const* d_in, const int* in_sizes, int n_in,
                              void* d_out, int out_size) {
    const float* x       = (const float*)d_in[0];
    const float* W_attn  = (const float*)d_in[1];
    const float* W_proj  = (const float*)d_in[2];
    const int*   indices = (const int*)d_in[3];
    float* out = (float*)d_out;

    static float* g_y_ptr = nullptr;
    const int attn_smem = (128 + 64 + 64 + 128) * STR * 4 + 64 * 4;   // ~104.7 KB
    if (g_y_ptr == nullptr) {
        cudaFuncSetAttribute(attn_kernel, cudaFuncAttributeMaxDynamicSharedMemorySize,
                             attn_smem);
        void* p = nullptr;
        cudaGetSymbolAddress(&p, g_y);
        g_y_ptr = (float*)p;
    }

    gemm_tf32<NQKV, true><<<dim3(NQKV / 128, NM / 128), 256>>>(x, W_attn, nullptr);

    int rope_threads = NB * NH * NT * 32;
    rope_kernel<<<rope_threads / 256, 256>>>(indices, 0);
    rope_kernel<<<rope_threads / 256, 256>>>(indices, 1);

    attn_kernel<<<dim3(NT / 128, NH, NB), 128, attn_smem>>>(indices);

    gemm_tf32<NC, false><<<dim3(NC / 128, NM / 128), 256>>>(g_y_ptr, W_proj, out);
}

// round 5
// speedup vs baseline: 3.2240x; 1.0747x over previous
#include <cuda_runtime.h>
#include <math.h>
#include <stdint.h>

// Problem constants
constexpr int NB = 4;       // batch
constexpr int NT = 2048;    // seq len
constexpr int NC = 1024;    // channels
constexpr int NH = 16;      // heads
constexpr int ND = 64;      // head dim
constexpr int NM = NB * NT;     // 8192 rows
constexpr int NQKV = 3 * NC;    // 3072

// Scratch (device globals — no runtime allocation)
__device__ float g_q[NB * NH * NT * ND];   // [B,H,T,D]  (tf32-rounded by rope)
__device__ float g_k[NB * NH * NT * ND];   // [B,H,T,D]  (tf32-rounded by rope)
__device__ float g_v[NB * NH * NT * ND];   // [B,H,T,D]  (tf32-rounded by gemm)
__device__ float g_y[NM * NC];             // [B*T, C]  (proj-friendly)

__device__ __forceinline__ float ftf32(float x) {
    float r;
    asm("cvt.rna.tf32.f32 %0, %1;" : "=f"(r) : "f"(x));
    return r;
}

__device__ __forceinline__ void mma_tf32(float* c, const uint32_t* a, const uint32_t* b) {
    asm volatile(
        "mma.sync.aligned.m16n8k8.row.col.f32.tf32.tf32.f32 "
        "{%0,%1,%2,%3}, {%4,%5,%6,%7}, {%8,%9}, {%0,%1,%2,%3};\n"
        : "+f"(c[0]), "+f"(c[1]), "+f"(c[2]), "+f"(c[3])
        : "r"(a[0]), "r"(a[1]), "r"(a[2]), "r"(a[3]), "r"(b[0]), "r"(b[1]));
}

__device__ __forceinline__ void cp16(uint32_t dst, const void* src) {
    asm volatile("cp.async.cg.shared.global [%0], [%1], 16;\n" :: "r"(dst), "l"(src));
}
__device__ __forceinline__ void cp_commit() {
    asm volatile("cp.async.commit_group;\n" ::: "memory");
}
__device__ __forceinline__ void cp_wait1() {
    asm volatile("cp.async.wait_group 1;\n" ::: "memory");
}

// ---------------------------------------------------------------------------
// TF32 tensor-core GEMM: C[M,N] = A[M,1024] @ B[1024,N]
// 128x128 tile, BK=16, double-buffered smem, 8 warps (2x4), warp tile 64x32.
// SCATTER=true: epilogue scatters into head-major g_q/g_k/g_v (QKV GEMM),
// with V tf32-rounded at the store (Q/K get rounded by rope after rotation).
// ---------------------------------------------------------------------------
template<int N, bool SCATTER>
__global__ __launch_bounds__(256, 2) void gemm_tf32(const float* __restrict__ A,
                                                    const float* __restrict__ B,
                                                    float* __restrict__ C) {
    __shared__ float As[2][16][136];
    __shared__ float Bs[2][16][136];
    const int bx = blockIdx.x, by = blockIdx.y;
    const int tid = threadIdx.x;
    const int w = tid >> 5, lane = tid & 31;
    const int qr = lane >> 2, qc = lane & 3;
    const int wm = (w >> 2) * 64, wn = (w & 3) * 32;
    const float* Ap = A + (size_t)(by * 128) * 1024;
    const float* Bp = B + bx * 128;

    float4 pa[2], pb[2];

    auto ldg = [&](int k0) {
#pragma unroll
        for (int t = 0; t < 2; t++) {
            int idx = tid * 2 + t;
            int r = idx >> 2, c4 = (idx & 3) * 4;
            pa[t] = *(const float4*)(Ap + (size_t)r * 1024 + k0 + c4);
            int rb = idx >> 5, cb = (idx & 31) * 4;
            pb[t] = *(const float4*)(Bp + (size_t)(k0 + rb) * N + cb);
        }
    };
    auto sts = [&](int s) {
#pragma unroll
        for (int t = 0; t < 2; t++) {
            int idx = tid * 2 + t;
            int r = idx >> 2, c4 = (idx & 3) * 4;
            As[s][c4 + 0][r] = ftf32(pa[t].x);
            As[s][c4 + 1][r] = ftf32(pa[t].y);
            As[s][c4 + 2][r] = ftf32(pa[t].z);
            As[s][c4 + 3][r] = ftf32(pa[t].w);
            int rb = idx >> 5, cb = (idx & 31) * 4;
            float4 v;
            v.x = ftf32(pb[t].x); v.y = ftf32(pb[t].y);
            v.z = ftf32(pb[t].z); v.w = ftf32(pb[t].w);
            *(float4*)&Bs[s][rb][cb] = v;
        }
    };

    float acc[4][4][4];
#pragma unroll
    for (int i = 0; i < 4; i++)
#pragma unroll
        for (int j = 0; j < 4; j++)
#pragma unroll
            for (int u = 0; u < 4; u++) acc[i][j][u] = 0.0f;

    ldg(0);
    sts(0);
    __syncthreads();
    int s = 0;
    for (int kt = 0; kt < 64; kt++) {
        if (kt < 63) ldg((kt + 1) * 16);
#pragma unroll
        for (int kc = 0; kc < 16; kc += 8) {
            uint32_t af[4][4], bf[4][2];
#pragma unroll
            for (int i = 0; i < 4; i++) {
                af[i][0] = __float_as_uint(As[s][kc + qc][wm + i * 16 + qr]);
                af[i][1] = __float_as_uint(As[s][kc + qc][wm + i * 16 + qr + 8]);
                af[i][2] = __float_as_uint(As[s][kc + qc + 4][wm + i * 16 + qr]);
                af[i][3] = __float_as_uint(As[s][kc + qc + 4][wm + i * 16 + qr + 8]);
            }
#pragma unroll
            for (int j = 0; j < 4; j++) {
                bf[j][0] = __float_as_uint(Bs[s][kc + qc][wn + j * 8 + qr]);
                bf[j][1] = __float_as_uint(Bs[s][kc + 4 + qc][wn + j * 8 + qr]);
            }
#pragma unroll
            for (int i = 0; i < 4; i++)
#pragma unroll
                for (int j = 0; j < 4; j++) mma_tf32(acc[i][j], af[i], bf[j]);
        }
        if (kt < 63) sts(s ^ 1);
        __syncthreads();
        s ^= 1;
    }

    // epilogue
#pragma unroll
    for (int i = 0; i < 4; i++) {
#pragma unroll
        for (int j = 0; j < 4; j++) {
            int r0 = by * 128 + wm + i * 16 + qr;
            int c0 = bx * 128 + wn + j * 8 + 2 * qc;
#pragma unroll
            for (int u = 0; u < 4; u++) {
                int row = r0 + (u >> 1) * 8;
                int col = c0 + (u & 1);
                if (SCATTER) {
                    int b = row >> 11;
                    int t = row & 2047;
                    int part = col >> 10;
                    int c = col & 1023;
                    int h = c >> 6;
                    int d = c & 63;
                    float* dst = (part == 0) ? g_q : (part == 1) ? g_k : g_v;
                    float val = (part == 2) ? ftf32(acc[i][j][u]) : acc[i][j][u];
                    dst[(size_t)(((b * NH + h) * NT) + t) * ND + d] = val;
                } else {
                    C[(size_t)row * NC + col] = acc[i][j][u];
                }
            }
        }
    }
}

// ---------------------------------------------------------------------------
// RoPE in-place on g_q / g_k; writes tf32-rounded outputs.
// ---------------------------------------------------------------------------
__global__ void rope_kernel(const int* __restrict__ indices, int which) {
    float* buf = which ? g_k : g_q;
    int gid = blockIdx.x * blockDim.x + threadIdx.x;
    int row = gid >> 5;                // [0, B*H*T)
    int i = gid & 31;                  // pair index (half = 32)
    int b = row >> 15;                 // / (H*T)
    int t = row & (NT - 1);
    int pos = indices[b * NT + t];
    float inv_freq = expf(-9.210340371976184f * (float)i * (1.0f / 32.0f));
    float ang = (float)pos * inv_freq;
    float sv, cv;
    sincosf(ang, &sv, &cv);
    size_t base = (size_t)row * ND;
    float x1 = buf[base + i];
    float x2 = buf[base + i + 32];
    buf[base + i]      = ftf32(x1 * cv - x2 * sv);
    buf[base + i + 32] = ftf32(x1 * sv + x2 * cv);
}

// ---------------------------------------------------------------------------
// Flash attention, TF32 tensor cores.
// Block = (qt of 128, h, b), 128 threads = 4 warps, 32 q-rows/warp (2 m-tiles).
// cp.async double-buffered K/V tiles; P kept in registers via shuffle
// transpose (C-frag -> A-frag), no P smem round trip.
// Smem layout (floats): Qs[128*68] | Ks[2][64*68] | Vs[2][64*72] | kidx[2][64]
// ---------------------------------------------------------------------------
constexpr int QSTR = 68;
constexpr int KSTR = 68;
constexpr int VSTR = 72;
constexpr int OFF_K = 128 * QSTR;                 // 8704
constexpr int OFF_V = OFF_K + 2 * 64 * KSTR;      // 17408
constexpr int OFF_I = OFF_V + 2 * 64 * VSTR;      // 26624
constexpr int SMEM_WORDS = OFF_I + 2 * 64;        // 26752 words = 107008 B

__global__ __launch_bounds__(128) void attn_kernel(const int* __restrict__ indices) {
    const int qt = (gridDim.x - 1) - blockIdx.x;   // heavy blocks first
    const int h = blockIdx.y;
    const int b = blockIdx.z;
    const int q0 = qt * 128;
    const int tid = threadIdx.x;
    const int w = tid >> 5, lane = tid & 31;
    const int qr = lane >> 2, qc = lane & 3;
    const int rw = w * 32;

    extern __shared__ float sm[];
    float* Qs = sm;
    const uint32_t smem_b = (uint32_t)__cvta_generic_to_shared(sm);

    const size_t head_base = (size_t)((b * NH + h) * NT) * ND;
    const float* kg_base = g_k + head_base;
    const float* vg_base = g_v + head_base;
    const int* idx_base = indices + b * NT;

    // issue cp.async for K/V tile kt into buffer buf
    auto issue_tile = [&](int kt, int buf) {
        const float* kg = kg_base + (size_t)(kt * 64) * ND;
        const float* vg = vg_base + (size_t)(kt * 64) * ND;
        uint32_t kdst = smem_b + (OFF_K + buf * 64 * KSTR) * 4;
        uint32_t vdst = smem_b + (OFF_V + buf * 64 * VSTR) * 4;
#pragma unroll
        for (int t = 0; t < 8; t++) {
            int idx = tid + t * 128;          // 0..1023
            int r = idx >> 4, c4 = (idx & 15) * 4;
            cp16(kdst + (r * KSTR + c4) * 4, kg + r * ND + c4);
            cp16(vdst + (r * VSTR + c4) * 4, vg + r * ND + c4);
        }
        if (tid < 16)
            cp16(smem_b + (OFF_I + buf * 64 + tid * 4) * 4, idx_base + kt * 64 + tid * 4);
    };

    // load Q tile (rope already tf32-rounded; scale applied post-MMA)
#pragma unroll
    for (int t = 0; t < 16; t++) {
        int idx = tid + t * 128;
        int r = idx >> 4, d4 = (idx & 15) * 4;
        *(float4*)&Qs[r * QSTR + d4] =
            *(const float4*)(g_q + head_base + (size_t)(q0 + r) * ND + d4);
    }
    int qi[4];
#pragma unroll
    for (int mi = 0; mi < 2; mi++) {
        qi[mi * 2 + 0] = idx_base[q0 + rw + mi * 16 + qr];
        qi[mi * 2 + 1] = idx_base[q0 + rw + mi * 16 + qr + 8];
    }

    float mrow[4], lrow[4];
#pragma unroll
    for (int u = 0; u < 4; u++) { mrow[u] = -INFINITY; lrow[u] = 0.0f; }
    float o[2][8][4];
#pragma unroll
    for (int mi = 0; mi < 2; mi++)
#pragma unroll
        for (int j = 0; j < 8; j++)
#pragma unroll
            for (int u = 0; u < 4; u++) o[mi][j][u] = 0.0f;

    const int ktmax = 2 * qt + 1;   // >= 1 always
    issue_tile(0, 0); cp_commit();
    issue_tile(1, 1); cp_commit();

    for (int kt = 0; kt <= ktmax; kt++) {
        const int buf = kt & 1;
        float* Ks = sm + OFF_K + buf * 64 * KSTR;
        float* Vs = sm + OFF_V + buf * 64 * VSTR;
        const int* kidx = (const int*)(sm + OFF_I + buf * 64);

        cp_wait1();          // tile kt landed (this thread's copies)
        __syncthreads();     // publish block-wide; prior readers of buf done

        // S = Q @ K^T : 2 m-tiles x 8 n-tiles, B-frags shared
        float s[2][8][4];
#pragma unroll
        for (int mi = 0; mi < 2; mi++)
#pragma unroll
            for (int j = 0; j < 8; j++)
#pragma unroll
                for (int u = 0; u < 4; u++) s[mi][j][u] = 0.0f;
#pragma unroll
        for (int kc = 0; kc < 8; kc++) {
            uint32_t af[2][4];
#pragma unroll
            for (int mi = 0; mi < 2; mi++) {
                int r0 = (rw + mi * 16 + qr) * QSTR + kc * 8 + qc;
                af[mi][0] = __float_as_uint(Qs[r0]);
                af[mi][1] = __float_as_uint(Qs[r0 + 8 * QSTR]);
                af[mi][2] = __float_as_uint(Qs[r0 + 4]);
                af[mi][3] = __float_as_uint(Qs[r0 + 8 * QSTR + 4]);
            }
#pragma unroll
            for (int j = 0; j < 8; j++) {
                uint32_t bf[2];
                bf[0] = __float_as_uint(Ks[(j * 8 + qr) * KSTR + kc * 8 + qc]);
                bf[1] = __float_as_uint(Ks[(j * 8 + qr) * KSTR + kc * 8 + qc + 4]);
                mma_tf32(s[0][j], af[0], bf);
                mma_tf32(s[1][j], af[1], bf);
            }
        }

        // scale + mask + online softmax (warp-local), P stays in registers
#pragma unroll
        for (int mi = 0; mi < 2; mi++) {
#pragma unroll
            for (int j = 0; j < 8; j++) {
                int c0 = j * 8 + 2 * qc;
                int kd0 = kidx[c0], kd1 = kidx[c0 + 1];
                s[mi][j][0] = (kd0 > qi[mi * 2 + 0]) ? -INFINITY : s[mi][j][0] * 0.125f;
                s[mi][j][1] = (kd1 > qi[mi * 2 + 0]) ? -INFINITY : s[mi][j][1] * 0.125f;
                s[mi][j][2] = (kd0 > qi[mi * 2 + 1]) ? -INFINITY : s[mi][j][2] * 0.125f;
                s[mi][j][3] = (kd1 > qi[mi * 2 + 1]) ? -INFINITY : s[mi][j][3] * 0.125f;
            }
            float tm0 = -INFINITY, tm1 = -INFINITY;
#pragma unroll
            for (int j = 0; j < 8; j++) {
                tm0 = fmaxf(tm0, fmaxf(s[mi][j][0], s[mi][j][1]));
                tm1 = fmaxf(tm1, fmaxf(s[mi][j][2], s[mi][j][3]));
            }
#pragma unroll
            for (int off = 1; off < 4; off <<= 1) {
                tm0 = fmaxf(tm0, __shfl_xor_sync(0xffffffffu, tm0, off));
                tm1 = fmaxf(tm1, __shfl_xor_sync(0xffffffffu, tm1, off));
            }
            float nm0 = fmaxf(mrow[mi * 2 + 0], tm0);
            float nm1 = fmaxf(mrow[mi * 2 + 1], tm1);
            float a0 = __expf(mrow[mi * 2 + 0] - nm0);
            float a1 = __expf(mrow[mi * 2 + 1] - nm1);
            mrow[mi * 2 + 0] = nm0; mrow[mi * 2 + 1] = nm1;
            float rs0 = 0.0f, rs1 = 0.0f;
#pragma unroll
            for (int j = 0; j < 8; j++) {
                s[mi][j][0] = ftf32(__expf(s[mi][j][0] - nm0));
                s[mi][j][1] = ftf32(__expf(s[mi][j][1] - nm0));
                s[mi][j][2] = ftf32(__expf(s[mi][j][2] - nm1));
                s[mi][j][3] = ftf32(__expf(s[mi][j][3] - nm1));
                rs0 += s[mi][j][0] + s[mi][j][1];
                rs1 += s[mi][j][2] + s[mi][j][3];
            }
#pragma unroll
            for (int off = 1; off < 4; off <<= 1) {
                rs0 += __shfl_xor_sync(0xffffffffu, rs0, off);
                rs1 += __shfl_xor_sync(0xffffffffu, rs1, off);
            }
            lrow[mi * 2 + 0] = lrow[mi * 2 + 0] * a0 + rs0;
            lrow[mi * 2 + 1] = lrow[mi * 2 + 1] * a1 + rs1;
#pragma unroll
            for (int j = 0; j < 8; j++) {
                o[mi][j][0] *= a0; o[mi][j][1] *= a0;
                o[mi][j][2] *= a1; o[mi][j][3] *= a1;
            }
        }

        // O += P @ V.  P C-frag -> A-frag via warp shuffles:
        // P[qr][qc] lives in lane qr*4+(qc>>1), slot qc&1.
        const int src0 = (lane & ~3) | (qc >> 1);
        const int src1 = src0 + 2;
        const bool odd = (qc & 1);
#pragma unroll
        for (int kc = 0; kc < 8; kc++) {
            uint32_t af[2][4];
#pragma unroll
            for (int mi = 0; mi < 2; mi++) {
                float p0 = s[mi][kc][0], p1 = s[mi][kc][1];
                float p2 = s[mi][kc][2], p3 = s[mi][kc][3];
                float t00 = __shfl_sync(0xffffffffu, p0, src0);
                float t01 = __shfl_sync(0xffffffffu, p1, src0);
                float t10 = __shfl_sync(0xffffffffu, p0, src1);
                float t11 = __shfl_sync(0xffffffffu, p1, src1);
                float u00 = __shfl_sync(0xffffffffu, p2, src0);
                float u01 = __shfl_sync(0xffffffffu, p3, src0);
                float u10 = __shfl_sync(0xffffffffu, p2, src1);
                float u11 = __shfl_sync(0xffffffffu, p3, src1);
                af[mi][0] = __float_as_uint(odd ? t01 : t00);
                af[mi][1] = __float_as_uint(odd ? u01 : u00);
                af[mi][2] = __float_as_uint(odd ? t11 : t10);
                af[mi][3] = __float_as_uint(odd ? u11 : u10);
            }
#pragma unroll
            for (int j = 0; j < 8; j++) {
                uint32_t bf[2];
                bf[0] = __float_as_uint(Vs[(kc * 8 + qc) * VSTR + j * 8 + qr]);
                bf[1] = __float_as_uint(Vs[(kc * 8 + qc + 4) * VSTR + j * 8 + qr]);
                mma_tf32(o[0][j], af[0], bf);
                mma_tf32(o[1][j], af[1], bf);
            }
        }

        __syncthreads();     // all warps done reading buf before refilling it
        if (kt + 2 <= ktmax) { issue_tile(kt + 2, buf); cp_commit(); }
    }

    // finalize: divide by l, write y to [B*T, C] layout
#pragma unroll
    for (int mi = 0; mi < 2; mi++) {
        float inv0 = 1.0f / lrow[mi * 2 + 0];
        float inv1 = 1.0f / lrow[mi * 2 + 1];
        size_t out0 = (size_t)(b * NT + q0 + rw + mi * 16 + qr) * NC + h * 64;
        size_t out1 = (size_t)(b * NT + q0 + rw + mi * 16 + qr + 8) * NC + h * 64;
#pragma unroll
        for (int j = 0; j < 8; j++) {
            int c0 = j * 8 + 2 * qc;
            float2 v0; v0.x = o[mi][j][0] * inv0; v0.y = o[mi][j][1] * inv0;
            float2 v1; v1.x = o[mi][j][2] * inv1; v1.y = o[mi][j][3] * inv1;
            *(float2*)&g_y[out0 + c0] = v0;
            *(float2*)&g_y[out1 + c0] = v1;
        }
    }
}

// ---------------------------------------------------------------------------
extern "C" void kernel_launch(void* const* d_in, const int* in_sizes, int n_in,
                              void* d_out, int out_size) {
    const float* x       = (const float*)d_in[0];
    const float* W_attn  = (const float*)d_in[1];
    const float* W_proj  = (const float*)d_in[2];
    const int*   indices = (const int*)d_in[3];
    float* out = (float*)d_out;

    static float* g_y_ptr = nullptr;
    const int attn_smem = SMEM_WORDS * 4;   // 107008 B
    if (g_y_ptr == nullptr) {
        cudaFuncSetAttribute(attn_kernel, cudaFuncAttributeMaxDynamicSharedMemorySize,
                             attn_smem);
        void* p = nullptr;
        cudaGetSymbolAddress(&p, g_y);
        g_y_ptr = (float*)p;
    }

    gemm_tf32<NQKV, true><<<dim3(NQKV / 128, NM / 128), 256>>>(x, W_attn, nullptr);

    int rope_threads = NB * NH * NT * 32;
    rope_kernel<<<rope_threads / 256, 256>>>(indices, 0);
    rope_kernel<<<rope_threads / 256, 256>>>(indices, 1);

    attn_kernel<<<dim3(NT / 128, NH, NB), 128, attn_smem>>>(indices);

    gemm_tf32<NC, false><<<dim3(NC / 128, NM / 128), 256>>>(g_y_ptr, W_proj, out);
}

// round 6
// speedup vs baseline: 3.7335x; 1.1580x over previous
#include <cuda_runtime.h>
#include <math.h>
#include <stdint.h>

// Problem constants
constexpr int NB = 4;       // batch
constexpr int NT = 2048;    // seq len
constexpr int NC = 1024;    // channels
constexpr int NH = 16;      // heads
constexpr int ND = 64;      // head dim
constexpr int NM = NB * NT;     // 8192 rows
constexpr int NQKV = 3 * NC;    // 3072

// Scratch (device globals — no runtime allocation)
__device__ float g_q[NB * NH * NT * ND];   // [B,H,T,D]  (tf32-rounded by rope)
__device__ float g_k[NB * NH * NT * ND];   // [B,H,T,D]  (tf32-rounded by rope)
__device__ float g_v[NB * NH * NT * ND];   // [B,H,T,D]  (tf32-rounded by gemm)
__device__ float g_y[NM * NC];             // [B*T, C]  (tf32-rounded by attn)
__device__ float g_xr[NM * NC];            // tf32-rounded x
__device__ float g_war[NC * NQKV];         // tf32-rounded W_attn
__device__ float g_wpr[NC * NC];           // tf32-rounded W_proj

__device__ __forceinline__ float ftf32(float x) {
    float r;
    asm("cvt.rna.tf32.f32 %0, %1;" : "=f"(r) : "f"(x));
    return r;
}

__device__ __forceinline__ void mma_tf32(float* c, const uint32_t* a, const uint32_t* b) {
    asm volatile(
        "mma.sync.aligned.m16n8k8.row.col.f32.tf32.tf32.f32 "
        "{%0,%1,%2,%3}, {%4,%5,%6,%7}, {%8,%9}, {%0,%1,%2,%3};\n"
        : "+f"(c[0]), "+f"(c[1]), "+f"(c[2]), "+f"(c[3])
        : "r"(a[0]), "r"(a[1]), "r"(a[2]), "r"(a[3]), "r"(b[0]), "r"(b[1]));
}

__device__ __forceinline__ void cp16(uint32_t dst, const void* src) {
    asm volatile("cp.async.cg.shared.global [%0], [%1], 16;\n" :: "r"(dst), "l"(src));
}
__device__ __forceinline__ void cp_commit() {
    asm volatile("cp.async.commit_group;\n" ::: "memory");
}
__device__ __forceinline__ void cp_wait1() {
    asm volatile("cp.async.wait_group 1;\n" ::: "memory");
}
__device__ __forceinline__ void cp_wait2() {
    asm volatile("cp.async.wait_group 2;\n" ::: "memory");
}

// ---------------------------------------------------------------------------
// Pre-round fp32 -> tf32 (vectorized grid-stride)
// ---------------------------------------------------------------------------
__global__ void round_kernel(const float4* __restrict__ src, float4* __restrict__ dst,
                             int n4) {
    int i = blockIdx.x * blockDim.x + threadIdx.x;
    int stride = gridDim.x * blockDim.x;
    for (; i < n4; i += stride) {
        float4 v = src[i];
        v.x = ftf32(v.x); v.y = ftf32(v.y); v.z = ftf32(v.z); v.w = ftf32(v.w);
        dst[i] = v;
    }
}

// ---------------------------------------------------------------------------
// TF32 tensor-core GEMM: C[M,N] = A[M,1024] @ B[1024,N]  (A,B pre-rounded tf32)
// 128x128 tile, BK=16, 4-stage cp.async pipeline, 8 warps (2x4), warp 64x32.
// Dynamic smem: A[4][128][20] | B[4][16][136]  (75776 B)
// SCATTER=true: epilogue scatters into head-major g_q/g_k/g_v (QKV GEMM).
// ---------------------------------------------------------------------------
constexpr int GA_STG = 128 * 20;   // floats per A stage
constexpr int GB_STG = 16 * 136;   // floats per B stage
constexpr int G_BOFF = 4 * GA_STG; // B region offset (floats)
constexpr int GEMM_SMEM = (G_BOFF + 4 * GB_STG) * 4;  // 75776 B

template<int N, bool SCATTER>
__global__ __launch_bounds__(256) void gemm_tf32(const float* __restrict__ A,
                                                 const float* __restrict__ B,
                                                 float* __restrict__ C) {
    extern __shared__ float smg[];
    const uint32_t smem_b = (uint32_t)__cvta_generic_to_shared(smg);
    const int bx = blockIdx.x, by = blockIdx.y;
    const int tid = threadIdx.x;
    const int w = tid >> 5, lane = tid & 31;
    const int qr = lane >> 2, qc = lane & 3;
    const int wm = (w >> 2) * 64, wn = (w & 3) * 32;
    const float* Ap = A + (size_t)(by * 128) * 1024;
    const float* Bp = B + bx * 128;

    // A tile: [m][k] stride 20; B tile: [k][n] stride 136
    auto issue = [&](int kt, int st) {
        const int k0 = kt * 16;
        uint32_t abase = smem_b + st * GA_STG * 4;
        uint32_t bbase = smem_b + (G_BOFF + st * GB_STG) * 4;
#pragma unroll
        for (int t = 0; t < 2; t++) {
            int idx = tid * 2 + t;
            int r = idx >> 2, c4 = (idx & 3) * 4;            // A: 128 rows x 16
            cp16(abase + (r * 20 + c4) * 4, Ap + (size_t)r * 1024 + k0 + c4);
            int rb = idx >> 5, cb = (idx & 31) * 4;          // B: 16 rows x 128
            cp16(bbase + (rb * 136 + cb) * 4, Bp + (size_t)(k0 + rb) * N + cb);
        }
        cp_commit();
    };

    float acc[4][4][4];
#pragma unroll
    for (int i = 0; i < 4; i++)
#pragma unroll
        for (int j = 0; j < 4; j++)
#pragma unroll
            for (int u = 0; u < 4; u++) acc[i][j][u] = 0.0f;

    issue(0, 0); issue(1, 1); issue(2, 2);

    for (int kt = 0; kt < 64; kt++) {
        const int st = kt & 3;
        const float* As = smg + st * GA_STG;
        const float* Bs = smg + G_BOFF + st * GB_STG;
        cp_wait2();          // stage kt landed
        __syncthreads();     // publish + prior readers of this buffer done
#pragma unroll
        for (int kc = 0; kc < 16; kc += 8) {
            uint32_t af[4][4], bf[4][2];
#pragma unroll
            for (int i = 0; i < 4; i++) {
                const float* ar = As + (wm + i * 16 + qr) * 20 + kc + qc;
                af[i][0] = __float_as_uint(ar[0]);
                af[i][1] = __float_as_uint(ar[8 * 20]);
                af[i][2] = __float_as_uint(ar[4]);
                af[i][3] = __float_as_uint(ar[8 * 20 + 4]);
            }
#pragma unroll
            for (int j = 0; j < 4; j++) {
                bf[j][0] = __float_as_uint(Bs[(kc + qc) * 136 + wn + j * 8 + qr]);
                bf[j][1] = __float_as_uint(Bs[(kc + 4 + qc) * 136 + wn + j * 8 + qr]);
            }
#pragma unroll
            for (int i = 0; i < 4; i++)
#pragma unroll
                for (int j = 0; j < 4; j++) mma_tf32(acc[i][j], af[i], bf[j]);
        }
        if (kt + 3 < 64) issue(kt + 3, (kt + 3) & 3);
    }

    // epilogue
#pragma unroll
    for (int i = 0; i < 4; i++) {
#pragma unroll
        for (int j = 0; j < 4; j++) {
            int r0 = by * 128 + wm + i * 16 + qr;
            int c0 = bx * 128 + wn + j * 8 + 2 * qc;
#pragma unroll
            for (int u = 0; u < 4; u++) {
                int row = r0 + (u >> 1) * 8;
                int col = c0 + (u & 1);
                if (SCATTER) {
                    int b = row >> 11;
                    int t = row & 2047;
                    int part = col >> 10;
                    int c = col & 1023;
                    int h = c >> 6;
                    int d = c & 63;
                    float* dst = (part == 0) ? g_q : (part == 1) ? g_k : g_v;
                    float val = (part == 2) ? ftf32(acc[i][j][u]) : acc[i][j][u];
                    dst[(size_t)(((b * NH + h) * NT) + t) * ND + d] = val;
                } else {
                    C[(size_t)row * NC + col] = acc[i][j][u];
                }
            }
        }
    }
}

// ---------------------------------------------------------------------------
// RoPE in-place on g_q AND g_k (blockIdx.y selects); tf32-rounded outputs.
// ---------------------------------------------------------------------------
__global__ void rope_kernel(const int* __restrict__ indices) {
    float* buf = blockIdx.y ? g_k : g_q;
    int gid = blockIdx.x * blockDim.x + threadIdx.x;
    int row = gid >> 5;                // [0, B*H*T)
    int i = gid & 31;                  // pair index (half = 32)
    int b = row >> 15;                 // / (H*T)
    int t = row & (NT - 1);
    int pos = indices[b * NT + t];
    float inv_freq = expf(-9.210340371976184f * (float)i * (1.0f / 32.0f));
    float ang = (float)pos * inv_freq;
    float sv, cv;
    sincosf(ang, &sv, &cv);
    size_t base = (size_t)row * ND;
    float x1 = buf[base + i];
    float x2 = buf[base + i + 32];
    buf[base + i]      = ftf32(x1 * cv - x2 * sv);
    buf[base + i + 32] = ftf32(x1 * sv + x2 * cv);
}

// ---------------------------------------------------------------------------
// Flash attention, TF32 tensor cores (unchanged from R5 except tf32 y write).
// ---------------------------------------------------------------------------
constexpr int QSTR = 68;
constexpr int KSTR = 68;
constexpr int VSTR = 72;
constexpr int OFF_K = 128 * QSTR;                 // 8704
constexpr int OFF_V = OFF_K + 2 * 64 * KSTR;      // 17408
constexpr int OFF_I = OFF_V + 2 * 64 * VSTR;      // 26624
constexpr int SMEM_WORDS = OFF_I + 2 * 64;        // 26752 words = 107008 B

__global__ __launch_bounds__(128) void attn_kernel(const int* __restrict__ indices) {
    const int qt = (gridDim.x - 1) - blockIdx.x;   // heavy blocks first
    const int h = blockIdx.y;
    const int b = blockIdx.z;
    const int q0 = qt * 128;
    const int tid = threadIdx.x;
    const int w = tid >> 5, lane = tid & 31;
    const int qr = lane >> 2, qc = lane & 3;
    const int rw = w * 32;

    extern __shared__ float sm[];
    float* Qs = sm;
    const uint32_t smem_b = (uint32_t)__cvta_generic_to_shared(sm);

    const size_t head_base = (size_t)((b * NH + h) * NT) * ND;
    const float* kg_base = g_k + head_base;
    const float* vg_base = g_v + head_base;
    const int* idx_base = indices + b * NT;

    auto issue_tile = [&](int kt, int buf) {
        const float* kg = kg_base + (size_t)(kt * 64) * ND;
        const float* vg = vg_base + (size_t)(kt * 64) * ND;
        uint32_t kdst = smem_b + (OFF_K + buf * 64 * KSTR) * 4;
        uint32_t vdst = smem_b + (OFF_V + buf * 64 * VSTR) * 4;
#pragma unroll
        for (int t = 0; t < 8; t++) {
            int idx = tid + t * 128;
            int r = idx >> 4, c4 = (idx & 15) * 4;
            cp16(kdst + (r * KSTR + c4) * 4, kg + r * ND + c4);
            cp16(vdst + (r * VSTR + c4) * 4, vg + r * ND + c4);
        }
        if (tid < 16)
            cp16(smem_b + (OFF_I + buf * 64 + tid * 4) * 4, idx_base + kt * 64 + tid * 4);
    };

#pragma unroll
    for (int t = 0; t < 16; t++) {
        int idx = tid + t * 128;
        int r = idx >> 4, d4 = (idx & 15) * 4;
        *(float4*)&Qs[r * QSTR + d4] =
            *(const float4*)(g_q + head_base + (size_t)(q0 + r) * ND + d4);
    }
    int qi[4];
#pragma unroll
    for (int mi = 0; mi < 2; mi++) {
        qi[mi * 2 + 0] = idx_base[q0 + rw + mi * 16 + qr];
        qi[mi * 2 + 1] = idx_base[q0 + rw + mi * 16 + qr + 8];
    }

    float mrow[4], lrow[4];
#pragma unroll
    for (int u = 0; u < 4; u++) { mrow[u] = -INFINITY; lrow[u] = 0.0f; }
    float o[2][8][4];
#pragma unroll
    for (int mi = 0; mi < 2; mi++)
#pragma unroll
        for (int j = 0; j < 8; j++)
#pragma unroll
            for (int u = 0; u < 4; u++) o[mi][j][u] = 0.0f;

    const int ktmax = 2 * qt + 1;
    issue_tile(0, 0); cp_commit();
    issue_tile(1, 1); cp_commit();

    for (int kt = 0; kt <= ktmax; kt++) {
        const int buf = kt & 1;
        float* Ks = sm + OFF_K + buf * 64 * KSTR;
        float* Vs = sm + OFF_V + buf * 64 * VSTR;
        const int* kidx = (const int*)(sm + OFF_I + buf * 64);

        cp_wait1();
        __syncthreads();

        float s[2][8][4];
#pragma unroll
        for (int mi = 0; mi < 2; mi++)
#pragma unroll
            for (int j = 0; j < 8; j++)
#pragma unroll
                for (int u = 0; u < 4; u++) s[mi][j][u] = 0.0f;
#pragma unroll
        for (int kc = 0; kc < 8; kc++) {
            uint32_t af[2][4];
#pragma unroll
            for (int mi = 0; mi < 2; mi++) {
                int r0 = (rw + mi * 16 + qr) * QSTR + kc * 8 + qc;
                af[mi][0] = __float_as_uint(Qs[r0]);
                af[mi][1] = __float_as_uint(Qs[r0 + 8 * QSTR]);
                af[mi][2] = __float_as_uint(Qs[r0 + 4]);
                af[mi][3] = __float_as_uint(Qs[r0 + 8 * QSTR + 4]);
            }
#pragma unroll
            for (int j = 0; j < 8; j++) {
                uint32_t bf[2];
                bf[0] = __float_as_uint(Ks[(j * 8 + qr) * KSTR + kc * 8 + qc]);
                bf[1] = __float_as_uint(Ks[(j * 8 + qr) * KSTR + kc * 8 + qc + 4]);
                mma_tf32(s[0][j], af[0], bf);
                mma_tf32(s[1][j], af[1], bf);
            }
        }

#pragma unroll
        for (int mi = 0; mi < 2; mi++) {
#pragma unroll
            for (int j = 0; j < 8; j++) {
                int c0 = j * 8 + 2 * qc;
                int kd0 = kidx[c0], kd1 = kidx[c0 + 1];
                s[mi][j][0] = (kd0 > qi[mi * 2 + 0]) ? -INFINITY : s[mi][j][0] * 0.125f;
                s[mi][j][1] = (kd1 > qi[mi * 2 + 0]) ? -INFINITY : s[mi][j][1] * 0.125f;
                s[mi][j][2] = (kd0 > qi[mi * 2 + 1]) ? -INFINITY : s[mi][j][2] * 0.125f;
                s[mi][j][3] = (kd1 > qi[mi * 2 + 1]) ? -INFINITY : s[mi][j][3] * 0.125f;
            }
            float tm0 = -INFINITY, tm1 = -INFINITY;
#pragma unroll
            for (int j = 0; j < 8; j++) {
                tm0 = fmaxf(tm0, fmaxf(s[mi][j][0], s[mi][j][1]));
                tm1 = fmaxf(tm1, fmaxf(s[mi][j][2], s[mi][j][3]));
            }
#pragma unroll
            for (int off = 1; off < 4; off <<= 1) {
                tm0 = fmaxf(tm0, __shfl_xor_sync(0xffffffffu, tm0, off));
                tm1 = fmaxf(tm1, __shfl_xor_sync(0xffffffffu, tm1, off));
            }
            float nm0 = fmaxf(mrow[mi * 2 + 0], tm0);
            float nm1 = fmaxf(mrow[mi * 2 + 1], tm1);
            float a0 = __expf(mrow[mi * 2 + 0] - nm0);
            float a1 = __expf(mrow[mi * 2 + 1] - nm1);
            mrow[mi * 2 + 0] = nm0; mrow[mi * 2 + 1] = nm1;
            float rs0 = 0.0f, rs1 = 0.0f;
#pragma unroll
            for (int j = 0; j < 8; j++) {
                s[mi][j][0] = ftf32(__expf(s[mi][j][0] - nm0));
                s[mi][j][1] = ftf32(__expf(s[mi][j][1] - nm0));
                s[mi][j][2] = ftf32(__expf(s[mi][j][2] - nm1));
                s[mi][j][3] = ftf32(__expf(s[mi][j][3] - nm1));
                rs0 += s[mi][j][0] + s[mi][j][1];
                rs1 += s[mi][j][2] + s[mi][j][3];
            }
#pragma unroll
            for (int off = 1; off < 4; off <<= 1) {
                rs0 += __shfl_xor_sync(0xffffffffu, rs0, off);
                rs1 += __shfl_xor_sync(0xffffffffu, rs1, off);
            }
            lrow[mi * 2 + 0] = lrow[mi * 2 + 0] * a0 + rs0;
            lrow[mi * 2 + 1] = lrow[mi * 2 + 1] * a1 + rs1;
#pragma unroll
            for (int j = 0; j < 8; j++) {
                o[mi][j][0] *= a0; o[mi][j][1] *= a0;
                o[mi][j][2] *= a1; o[mi][j][3] *= a1;
            }
        }

        const int src0 = (lane & ~3) | (qc >> 1);
        const int src1 = src0 + 2;
        const bool odd = (qc & 1);
#pragma unroll
        for (int kc = 0; kc < 8; kc++) {
            uint32_t af[2][4];
#pragma unroll
            for (int mi = 0; mi < 2; mi++) {
                float p0 = s[mi][kc][0], p1 = s[mi][kc][1];
                float p2 = s[mi][kc][2], p3 = s[mi][kc][3];
                float t00 = __shfl_sync(0xffffffffu, p0, src0);
                float t01 = __shfl_sync(0xffffffffu, p1, src0);
                float t10 = __shfl_sync(0xffffffffu, p0, src1);
                float t11 = __shfl_sync(0xffffffffu, p1, src1);
                float u00 = __shfl_sync(0xffffffffu, p2, src0);
                float u01 = __shfl_sync(0xffffffffu, p3, src0);
                float u10 = __shfl_sync(0xffffffffu, p2, src1);
                float u11 = __shfl_sync(0xffffffffu, p3, src1);
                af[mi][0] = __float_as_uint(odd ? t01 : t00);
                af[mi][1] = __float_as_uint(odd ? u01 : u00);
                af[mi][2] = __float_as_uint(odd ? t11 : t10);
                af[mi][3] = __float_as_uint(odd ? u11 : u10);
            }
#pragma unroll
            for (int j = 0; j < 8; j++) {
                uint32_t bf[2];
                bf[0] = __float_as_uint(Vs[(kc * 8 + qc) * VSTR + j * 8 + qr]);
                bf[1] = __float_as_uint(Vs[(kc * 8 + qc + 4) * VSTR + j * 8 + qr]);
                mma_tf32(o[0][j], af[0], bf);
                mma_tf32(o[1][j], af[1], bf);
            }
        }

        __syncthreads();
        if (kt + 2 <= ktmax) { issue_tile(kt + 2, buf); cp_commit(); }
    }

    // finalize: divide by l, tf32-round (proj GEMM consumes via cp.async)
#pragma unroll
    for (int mi = 0; mi < 2; mi++) {
        float inv0 = 1.0f / lrow[mi * 2 + 0];
        float inv1 = 1.0f / lrow[mi * 2 + 1];
        size_t out0 = (size_t)(b * NT + q0 + rw + mi * 16 + qr) * NC + h * 64;
        size_t out1 = (size_t)(b * NT + q0 + rw + mi * 16 + qr + 8) * NC + h * 64;
#pragma unroll
        for (int j = 0; j < 8; j++) {
            int c0 = j * 8 + 2 * qc;
            float2 v0; v0.x = ftf32(o[mi][j][0] * inv0); v0.y = ftf32(o[mi][j][1] * inv0);
            float2 v1; v1.x = ftf32(o[mi][j][2] * inv1); v1.y = ftf32(o[mi][j][3] * inv1);
            *(float2*)&g_y[out0 + c0] = v0;
            *(float2*)&g_y[out1 + c0] = v1;
        }
    }
}

// ---------------------------------------------------------------------------
extern "C" void kernel_launch(void* const* d_in, const int* in_sizes, int n_in,
                              void* d_out, int out_size) {
    const float* x       = (const float*)d_in[0];
    const float* W_attn  = (const float*)d_in[1];
    const float* W_proj  = (const float*)d_in[2];
    const int*   indices = (const int*)d_in[3];
    float* out = (float*)d_out;

    static float *p_y = nullptr, *p_xr = nullptr, *p_war = nullptr, *p_wpr = nullptr;
    const int attn_smem = SMEM_WORDS * 4;   // 107008 B
    if (p_y == nullptr) {
        cudaFuncSetAttribute(attn_kernel, cudaFuncAttributeMaxDynamicSharedMemorySize,
                             attn_smem);
        cudaFuncSetAttribute(gemm_tf32<NQKV, true>,
                             cudaFuncAttributeMaxDynamicSharedMemorySize, GEMM_SMEM);
        cudaFuncSetAttribute(gemm_tf32<NC, false>,
                             cudaFuncAttributeMaxDynamicSharedMemorySize, GEMM_SMEM);
        void* p;
        cudaGetSymbolAddress(&p, g_y);   p_y   = (float*)p;
        cudaGetSymbolAddress(&p, g_xr);  p_xr  = (float*)p;
        cudaGetSymbolAddress(&p, g_war); p_war = (float*)p;
        cudaGetSymbolAddress(&p, g_wpr); p_wpr = (float*)p;
    }

    // pre-round inputs to tf32 (cp.async pipelines can't convert in flight)
    round_kernel<<<592, 256>>>((const float4*)x, (float4*)p_xr, NM * NC / 4);
    round_kernel<<<592, 256>>>((const float4*)W_attn, (float4*)p_war, NC * NQKV / 4);
    round_kernel<<<592, 256>>>((const float4*)W_proj, (float4*)p_wpr, NC * NC / 4);

    gemm_tf32<NQKV, true><<<dim3(NQKV / 128, NM / 128), 256, GEMM_SMEM>>>(
        p_xr, p_war, nullptr);

    int rope_threads = NB * NH * NT * 32;
    rope_kernel<<<dim3(rope_threads / 256, 2), 256>>>(indices);

    attn_kernel<<<dim3(NT / 128, NH, NB), 128, attn_smem>>>(indices);

    gemm_tf32<NC, false><<<dim3(NC / 128, NM / 128), 256, GEMM_SMEM>>>(
        p_y, p_wpr, out);
}

// round 7
// speedup vs baseline: 4.0925x; 1.0962x over previous
#include <cuda_runtime.h>
#include <math.h>
#include <stdint.h>

// Problem constants
constexpr int NB = 4;       // batch
constexpr int NT = 2048;    // seq len
constexpr int NC = 1024;    // channels
constexpr int NH = 16;      // heads
constexpr int ND = 64;      // head dim
constexpr int NM = NB * NT;     // 8192 rows
constexpr int NQKV = 3 * NC;    // 3072

// Scratch (device globals — no runtime allocation)
__device__ float g_q[NB * NH * NT * ND];   // [B,H,T,D]  (tf32-rounded by rope)
__device__ float g_k[NB * NH * NT * ND];   // [B,H,T,D]  (tf32-rounded by rope)
__device__ float g_v[NB * NH * NT * ND];   // [B,H,T,D]  (tf32-rounded by gemm)
__device__ float g_y[NM * NC];             // [B*T, C]  (tf32-rounded by attn)
__device__ float g_xr[NM * NC];            // tf32-rounded x
__device__ float g_war[NC * NQKV];         // tf32-rounded W_attn
__device__ float g_wpr[NC * NC];           // tf32-rounded W_proj

__device__ __forceinline__ float ftf32(float x) {
    float r;
    asm("cvt.rna.tf32.f32 %0, %1;" : "=f"(r) : "f"(x));
    return r;
}

__device__ __forceinline__ void mma_tf32(float* c, const uint32_t* a, const uint32_t* b) {
    asm volatile(
        "mma.sync.aligned.m16n8k8.row.col.f32.tf32.tf32.f32 "
        "{%0,%1,%2,%3}, {%4,%5,%6,%7}, {%8,%9}, {%0,%1,%2,%3};\n"
        : "+f"(c[0]), "+f"(c[1]), "+f"(c[2]), "+f"(c[3])
        : "r"(a[0]), "r"(a[1]), "r"(a[2]), "r"(a[3]), "r"(b[0]), "r"(b[1]));
}

__device__ __forceinline__ void cp16(uint32_t dst, const void* src) {
    asm volatile("cp.async.cg.shared.global [%0], [%1], 16;\n" :: "r"(dst), "l"(src));
}
__device__ __forceinline__ void cp_commit() {
    asm volatile("cp.async.commit_group;\n" ::: "memory");
}
__device__ __forceinline__ void cp_wait1() {
    asm volatile("cp.async.wait_group 1;\n" ::: "memory");
}

// ---------------------------------------------------------------------------
// Pre-round fp32 -> tf32 (vectorized grid-stride)
// ---------------------------------------------------------------------------
__global__ void round_kernel(const float4* __restrict__ src, float4* __restrict__ dst,
                             int n4) {
    int i = blockIdx.x * blockDim.x + threadIdx.x;
    int stride = gridDim.x * blockDim.x;
    for (; i < n4; i += stride) {
        float4 v = src[i];
        v.x = ftf32(v.x); v.y = ftf32(v.y); v.z = ftf32(v.z); v.w = ftf32(v.w);
        dst[i] = v;
    }
}

// ---------------------------------------------------------------------------
// TF32 tensor-core GEMM: C[M,N] = A[M,1024] @ B[1024,N]  (A,B pre-rounded tf32)
// 128x128 tile, BK=32, 3-stage cp.async pipeline, 8 warps (2x4), warp 64x32.
// Next stage issued right after the sync (full-tile latency cover); only 32
// sync boundaries (was 64), 64 MMAs/warp per boundary (was 32).
// Dynamic smem: A[3][128][36] | B[3][32][136]  (107520 B)
// SCATTER=true: epilogue scatters into head-major g_q/g_k/g_v (QKV GEMM).
// ---------------------------------------------------------------------------
constexpr int GA_STG = 128 * 36;   // floats per A stage
constexpr int GB_STG = 32 * 136;   // floats per B stage
constexpr int G_BOFF = 3 * GA_STG; // B region offset (floats)
constexpr int GEMM_SMEM = (G_BOFF + 3 * GB_STG) * 4;  // 107520 B

template<int N, bool SCATTER>
__global__ __launch_bounds__(256) void gemm_tf32(const float* __restrict__ A,
                                                 const float* __restrict__ B,
                                                 float* __restrict__ C) {
    extern __shared__ float smg[];
    const uint32_t smem_b = (uint32_t)__cvta_generic_to_shared(smg);
    const int bx = blockIdx.x, by = blockIdx.y;
    const int tid = threadIdx.x;
    const int w = tid >> 5, lane = tid & 31;
    const int qr = lane >> 2, qc = lane & 3;
    const int wm = (w >> 2) * 64, wn = (w & 3) * 32;
    const float* Ap = A + (size_t)(by * 128) * 1024;
    const float* Bp = B + bx * 128;

    // A tile: [m][k] stride 36 (==4 mod 32); B tile: [k][n] stride 136 (==8 mod 32)
    auto issue = [&](int kt, int st) {
        const int k0 = kt * 32;
        uint32_t abase = smem_b + st * GA_STG * 4;
        uint32_t bbase = smem_b + (G_BOFF + st * GB_STG) * 4;
#pragma unroll
        for (int t = 0; t < 4; t++) {
            int idx = tid + t * 256;                          // 0..1023
            int r = idx >> 3, c4 = (idx & 7) * 4;             // A: 128 x 32
            cp16(abase + (r * 36 + c4) * 4, Ap + (size_t)r * 1024 + k0 + c4);
            int rb = idx >> 5, cb = (idx & 31) * 4;           // B: 32 x 128
            cp16(bbase + (rb * 136 + cb) * 4, Bp + (size_t)(k0 + rb) * N + cb);
        }
        cp_commit();
    };

    float acc[4][4][4];
#pragma unroll
    for (int i = 0; i < 4; i++)
#pragma unroll
        for (int j = 0; j < 4; j++)
#pragma unroll
            for (int u = 0; u < 4; u++) acc[i][j][u] = 0.0f;

    issue(0, 0); issue(1, 1);

    for (int kt = 0; kt < 32; kt++) {
        const int st = kt % 3;
        cp_wait1();          // stage kt landed (1 outstanding = kt+1)
        __syncthreads();     // publish + all readers of stage (kt-1) done
        if (kt + 2 < 32) issue(kt + 2, (kt + 2) % 3);
        const float* As = smg + st * GA_STG;
        const float* Bs = smg + G_BOFF + st * GB_STG;
#pragma unroll
        for (int kc = 0; kc < 32; kc += 8) {
            uint32_t af[4][4], bf[4][2];
#pragma unroll
            for (int i = 0; i < 4; i++) {
                const float* ar = As + (wm + i * 16 + qr) * 36 + kc + qc;
                af[i][0] = __float_as_uint(ar[0]);
                af[i][1] = __float_as_uint(ar[8 * 36]);
                af[i][2] = __float_as_uint(ar[4]);
                af[i][3] = __float_as_uint(ar[8 * 36 + 4]);
            }
#pragma unroll
            for (int j = 0; j < 4; j++) {
                bf[j][0] = __float_as_uint(Bs[(kc + qc) * 136 + wn + j * 8 + qr]);
                bf[j][1] = __float_as_uint(Bs[(kc + 4 + qc) * 136 + wn + j * 8 + qr]);
            }
#pragma unroll
            for (int i = 0; i < 4; i++)
#pragma unroll
                for (int j = 0; j < 4; j++) mma_tf32(acc[i][j], af[i], bf[j]);
        }
    }

    // epilogue
#pragma unroll
    for (int i = 0; i < 4; i++) {
#pragma unroll
        for (int j = 0; j < 4; j++) {
            int r0 = by * 128 + wm + i * 16 + qr;
            int c0 = bx * 128 + wn + j * 8 + 2 * qc;
#pragma unroll
            for (int u = 0; u < 4; u++) {
                int row = r0 + (u >> 1) * 8;
                int col = c0 + (u & 1);
                if (SCATTER) {
                    int b = row >> 11;
                    int t = row & 2047;
                    int part = col >> 10;
                    int c = col & 1023;
                    int h = c >> 6;
                    int d = c & 63;
                    float* dst = (part == 0) ? g_q : (part == 1) ? g_k : g_v;
                    float val = (part == 2) ? ftf32(acc[i][j][u]) : acc[i][j][u];
                    dst[(size_t)(((b * NH + h) * NT) + t) * ND + d] = val;
                } else {
                    C[(size_t)row * NC + col] = acc[i][j][u];
                }
            }
        }
    }
}

// ---------------------------------------------------------------------------
// RoPE in-place on g_q AND g_k (blockIdx.y selects); tf32-rounded outputs.
// ---------------------------------------------------------------------------
__global__ void rope_kernel(const int* __restrict__ indices) {
    float* buf = blockIdx.y ? g_k : g_q;
    int gid = blockIdx.x * blockDim.x + threadIdx.x;
    int row = gid >> 5;                // [0, B*H*T)
    int i = gid & 31;                  // pair index (half = 32)
    int b = row >> 15;                 // / (H*T)
    int t = row & (NT - 1);
    int pos = indices[b * NT + t];
    float inv_freq = expf(-9.210340371976184f * (float)i * (1.0f / 32.0f));
    float ang = (float)pos * inv_freq;
    float sv, cv;
    sincosf(ang, &sv, &cv);
    size_t base = (size_t)row * ND;
    float x1 = buf[base + i];
    float x2 = buf[base + i + 32];
    buf[base + i]      = ftf32(x1 * cv - x2 * sv);
    buf[base + i + 32] = ftf32(x1 * sv + x2 * cv);
}

// ---------------------------------------------------------------------------
// Flash attention, TF32 tensor cores (unchanged from R6).
// ---------------------------------------------------------------------------
constexpr int QSTR = 68;
constexpr int KSTR = 68;
constexpr int VSTR = 72;
constexpr int OFF_K = 128 * QSTR;                 // 8704
constexpr int OFF_V = OFF_K + 2 * 64 * KSTR;      // 17408
constexpr int OFF_I = OFF_V + 2 * 64 * VSTR;      // 26624
constexpr int SMEM_WORDS = OFF_I + 2 * 64;        // 26752 words = 107008 B

__global__ __launch_bounds__(128) void attn_kernel(const int* __restrict__ indices) {
    const int qt = (gridDim.x - 1) - blockIdx.x;   // heavy blocks first
    const int h = blockIdx.y;
    const int b = blockIdx.z;
    const int q0 = qt * 128;
    const int tid = threadIdx.x;
    const int w = tid >> 5, lane = tid & 31;
    const int qr = lane >> 2, qc = lane & 3;
    const int rw = w * 32;

    extern __shared__ float sm[];
    float* Qs = sm;
    const uint32_t smem_b = (uint32_t)__cvta_generic_to_shared(sm);

    const size_t head_base = (size_t)((b * NH + h) * NT) * ND;
    const float* kg_base = g_k + head_base;
    const float* vg_base = g_v + head_base;
    const int* idx_base = indices + b * NT;

    auto issue_tile = [&](int kt, int buf) {
        const float* kg = kg_base + (size_t)(kt * 64) * ND;
        const float* vg = vg_base + (size_t)(kt * 64) * ND;
        uint32_t kdst = smem_b + (OFF_K + buf * 64 * KSTR) * 4;
        uint32_t vdst = smem_b + (OFF_V + buf * 64 * VSTR) * 4;
#pragma unroll
        for (int t = 0; t < 8; t++) {
            int idx = tid + t * 128;
            int r = idx >> 4, c4 = (idx & 15) * 4;
            cp16(kdst + (r * KSTR + c4) * 4, kg + r * ND + c4);
            cp16(vdst + (r * VSTR + c4) * 4, vg + r * ND + c4);
        }
        if (tid < 16)
            cp16(smem_b + (OFF_I + buf * 64 + tid * 4) * 4, idx_base + kt * 64 + tid * 4);
    };

#pragma unroll
    for (int t = 0; t < 16; t++) {
        int idx = tid + t * 128;
        int r = idx >> 4, d4 = (idx & 15) * 4;
        *(float4*)&Qs[r * QSTR + d4] =
            *(const float4*)(g_q + head_base + (size_t)(q0 + r) * ND + d4);
    }
    int qi[4];
#pragma unroll
    for (int mi = 0; mi < 2; mi++) {
        qi[mi * 2 + 0] = idx_base[q0 + rw + mi * 16 + qr];
        qi[mi * 2 + 1] = idx_base[q0 + rw + mi * 16 + qr + 8];
    }

    float mrow[4], lrow[4];
#pragma unroll
    for (int u = 0; u < 4; u++) { mrow[u] = -INFINITY; lrow[u] = 0.0f; }
    float o[2][8][4];
#pragma unroll
    for (int mi = 0; mi < 2; mi++)
#pragma unroll
        for (int j = 0; j < 8; j++)
#pragma unroll
            for (int u = 0; u < 4; u++) o[mi][j][u] = 0.0f;

    const int ktmax = 2 * qt + 1;
    issue_tile(0, 0); cp_commit();
    issue_tile(1, 1); cp_commit();

    for (int kt = 0; kt <= ktmax; kt++) {
        const int buf = kt & 1;
        float* Ks = sm + OFF_K + buf * 64 * KSTR;
        float* Vs = sm + OFF_V + buf * 64 * VSTR;
        const int* kidx = (const int*)(sm + OFF_I + buf * 64);

        cp_wait1();
        __syncthreads();

        float s[2][8][4];
#pragma unroll
        for (int mi = 0; mi < 2; mi++)
#pragma unroll
            for (int j = 0; j < 8; j++)
#pragma unroll
                for (int u = 0; u < 4; u++) s[mi][j][u] = 0.0f;
#pragma unroll
        for (int kc = 0; kc < 8; kc++) {
            uint32_t af[2][4];
#pragma unroll
            for (int mi = 0; mi < 2; mi++) {
                int r0 = (rw + mi * 16 + qr) * QSTR + kc * 8 + qc;
                af[mi][0] = __float_as_uint(Qs[r0]);
                af[mi][1] = __float_as_uint(Qs[r0 + 8 * QSTR]);
                af[mi][2] = __float_as_uint(Qs[r0 + 4]);
                af[mi][3] = __float_as_uint(Qs[r0 + 8 * QSTR + 4]);
            }
#pragma unroll
            for (int j = 0; j < 8; j++) {
                uint32_t bf[2];
                bf[0] = __float_as_uint(Ks[(j * 8 + qr) * KSTR + kc * 8 + qc]);
                bf[1] = __float_as_uint(Ks[(j * 8 + qr) * KSTR + kc * 8 + qc + 4]);
                mma_tf32(s[0][j], af[0], bf);
                mma_tf32(s[1][j], af[1], bf);
            }
        }

#pragma unroll
        for (int mi = 0; mi < 2; mi++) {
#pragma unroll
            for (int j = 0; j < 8; j++) {
                int c0 = j * 8 + 2 * qc;
                int kd0 = kidx[c0], kd1 = kidx[c0 + 1];
                s[mi][j][0] = (kd0 > qi[mi * 2 + 0]) ? -INFINITY : s[mi][j][0] * 0.125f;
                s[mi][j][1] = (kd1 > qi[mi * 2 + 0]) ? -INFINITY : s[mi][j][1] * 0.125f;
                s[mi][j][2] = (kd0 > qi[mi * 2 + 1]) ? -INFINITY : s[mi][j][2] * 0.125f;
                s[mi][j][3] = (kd1 > qi[mi * 2 + 1]) ? -INFINITY : s[mi][j][3] * 0.125f;
            }
            float tm0 = -INFINITY, tm1 = -INFINITY;
#pragma unroll
            for (int j = 0; j < 8; j++) {
                tm0 = fmaxf(tm0, fmaxf(s[mi][j][0], s[mi][j][1]));
                tm1 = fmaxf(tm1, fmaxf(s[mi][j][2], s[mi][j][3]));
            }
#pragma unroll
            for (int off = 1; off < 4; off <<= 1) {
                tm0 = fmaxf(tm0, __shfl_xor_sync(0xffffffffu, tm0, off));
                tm1 = fmaxf(tm1, __shfl_xor_sync(0xffffffffu, tm1, off));
            }
            float nm0 = fmaxf(mrow[mi * 2 + 0], tm0);
            float nm1 = fmaxf(mrow[mi * 2 + 1], tm1);
            float a0 = __expf(mrow[mi * 2 + 0] - nm0);
            float a1 = __expf(mrow[mi * 2 + 1] - nm1);
            mrow[mi * 2 + 0] = nm0; mrow[mi * 2 + 1] = nm1;
            float rs0 = 0.0f, rs1 = 0.0f;
#pragma unroll
            for (int j = 0; j < 8; j++) {
                s[mi][j][0] = ftf32(__expf(s[mi][j][0] - nm0));
                s[mi][j][1] = ftf32(__expf(s[mi][j][1] - nm0));
                s[mi][j][2] = ftf32(__expf(s[mi][j][2] - nm1));
                s[mi][j][3] = ftf32(__expf(s[mi][j][3] - nm1));
                rs0 += s[mi][j][0] + s[mi][j][1];
                rs1 += s[mi][j][2] + s[mi][j][3];
            }
#pragma unroll
            for (int off = 1; off < 4; off <<= 1) {
                rs0 += __shfl_xor_sync(0xffffffffu, rs0, off);
                rs1 += __shfl_xor_sync(0xffffffffu, rs1, off);
            }
            lrow[mi * 2 + 0] = lrow[mi * 2 + 0] * a0 + rs0;
            lrow[mi * 2 + 1] = lrow[mi * 2 + 1] * a1 + rs1;
#pragma unroll
            for (int j = 0; j < 8; j++) {
                o[mi][j][0] *= a0; o[mi][j][1] *= a0;
                o[mi][j][2] *= a1; o[mi][j][3] *= a1;
            }
        }

        const int src0 = (lane & ~3) | (qc >> 1);
        const int src1 = src0 + 2;
        const bool odd = (qc & 1);
#pragma unroll
        for (int kc = 0; kc < 8; kc++) {
            uint32_t af[2][4];
#pragma unroll
            for (int mi = 0; mi < 2; mi++) {
                float p0 = s[mi][kc][0], p1 = s[mi][kc][1];
                float p2 = s[mi][kc][2], p3 = s[mi][kc][3];
                float t00 = __shfl_sync(0xffffffffu, p0, src0);
                float t01 = __shfl_sync(0xffffffffu, p1, src0);
                float t10 = __shfl_sync(0xffffffffu, p0, src1);
                float t11 = __shfl_sync(0xffffffffu, p1, src1);
                float u00 = __shfl_sync(0xffffffffu, p2, src0);
                float u01 = __shfl_sync(0xffffffffu, p3, src0);
                float u10 = __shfl_sync(0xffffffffu, p2, src1);
                float u11 = __shfl_sync(0xffffffffu, p3, src1);
                af[mi][0] = __float_as_uint(odd ? t01 : t00);
                af[mi][1] = __float_as_uint(odd ? u01 : u00);
                af[mi][2] = __float_as_uint(odd ? t11 : t10);
                af[mi][3] = __float_as_uint(odd ? u11 : u10);
            }
#pragma unroll
            for (int j = 0; j < 8; j++) {
                uint32_t bf[2];
                bf[0] = __float_as_uint(Vs[(kc * 8 + qc) * VSTR + j * 8 + qr]);
                bf[1] = __float_as_uint(Vs[(kc * 8 + qc + 4) * VSTR + j * 8 + qr]);
                mma_tf32(o[0][j], af[0], bf);
                mma_tf32(o[1][j], af[1], bf);
            }
        }

        __syncthreads();
        if (kt + 2 <= ktmax) { issue_tile(kt + 2, buf); cp_commit(); }
    }

    // finalize: divide by l, tf32-round (proj GEMM consumes directly)
#pragma unroll
    for (int mi = 0; mi < 2; mi++) {
        float inv0 = 1.0f / lrow[mi * 2 + 0];
        float inv1 = 1.0f / lrow[mi * 2 + 1];
        size_t out0 = (size_t)(b * NT + q0 + rw + mi * 16 + qr) * NC + h * 64;
        size_t out1 = (size_t)(b * NT + q0 + rw + mi * 16 + qr + 8) * NC + h * 64;
#pragma unroll
        for (int j = 0; j < 8; j++) {
            int c0 = j * 8 + 2 * qc;
            float2 v0; v0.x = ftf32(o[mi][j][0] * inv0); v0.y = ftf32(o[mi][j][1] * inv0);
            float2 v1; v1.x = ftf32(o[mi][j][2] * inv1); v1.y = ftf32(o[mi][j][3] * inv1);
            *(float2*)&g_y[out0 + c0] = v0;
            *(float2*)&g_y[out1 + c0] = v1;
        }
    }
}

// ---------------------------------------------------------------------------
extern "C" void kernel_launch(void* const* d_in, const int* in_sizes, int n_in,
                              void* d_out, int out_size) {
    const float* x       = (const float*)d_in[0];
    const float* W_attn  = (const float*)d_in[1];
    const float* W_proj  = (const float*)d_in[2];
    const int*   indices = (const int*)d_in[3];
    float* out = (float*)d_out;

    static float *p_y = nullptr, *p_xr = nullptr, *p_war = nullptr, *p_wpr = nullptr;
    const int attn_smem = SMEM_WORDS * 4;   // 107008 B
    if (p_y == nullptr) {
        cudaFuncSetAttribute(attn_kernel, cudaFuncAttributeMaxDynamicSharedMemorySize,
                             attn_smem);
        cudaFuncSetAttribute(gemm_tf32<NQKV, true>,
                             cudaFuncAttributeMaxDynamicSharedMemorySize, GEMM_SMEM);
        cudaFuncSetAttribute(gemm_tf32<NC, false>,
                             cudaFuncAttributeMaxDynamicSharedMemorySize, GEMM_SMEM);
        void* p;
        cudaGetSymbolAddress(&p, g_y);   p_y   = (float*)p;
        cudaGetSymbolAddress(&p, g_xr);  p_xr  = (float*)p;
        cudaGetSymbolAddress(&p, g_war); p_war = (float*)p;
        cudaGetSymbolAddress(&p, g_wpr); p_wpr = (float*)p;
    }

    // pre-round inputs to tf32 (cp.async pipelines can't convert in flight)
    round_kernel<<<592, 256>>>((const float4*)x, (float4*)p_xr, NM * NC / 4);
    round_kernel<<<592, 256>>>((const float4*)W_attn, (float4*)p_war, NC * NQKV / 4);
    round_kernel<<<592, 256>>>((const float4*)W_proj, (float4*)p_wpr, NC * NC / 4);

    gemm_tf32<NQKV, true><<<dim3(NQKV / 128, NM / 128), 256, GEMM_SMEM>>>(
        p_xr, p_war, nullptr);

    int rope_threads = NB * NH * NT * 32;
    rope_kernel<<<dim3(rope_threads / 256, 2), 256>>>(indices);

    attn_kernel<<<dim3(NT / 128, NH, NB), 128, attn_smem>>>(indices);

    gemm_tf32<NC, false><<<dim3(NC / 128, NM / 128), 256, GEMM_SMEM>>>(
        p_y, p_wpr, out);
}

// round 8
// speedup vs baseline: 4.1479x; 1.0135x over previous
#include <cuda_runtime.h>
#include <math.h>
#include <stdint.h>

// Problem constants
constexpr int NB = 4;       // batch
constexpr int NT = 2048;    // seq len
constexpr int NC = 1024;    // channels
constexpr int NH = 16;      // heads
constexpr int ND = 64;      // head dim
constexpr int NM = NB * NT;     // 8192 rows
constexpr int NQKV = 3 * NC;    // 3072

// Scratch (device globals — no runtime allocation)
__device__ float g_q[NB * NH * NT * ND];   // [B,H,T,D]  (rope+tf32 by gemm epilogue)
__device__ float g_k[NB * NH * NT * ND];   // [B,H,T,D]  (rope+tf32 by gemm epilogue)
__device__ float g_v[NB * NH * NT * ND];   // [B,H,T,D]  (tf32-rounded by gemm)
__device__ float g_y[NM * NC];             // [B*T, C]  (tf32-rounded by attn)
__device__ float g_xr[NM * NC];            // tf32-rounded x
__device__ float g_war[NC * NQKV];         // tf32-rounded W_attn
__device__ float g_wpr[NC * NC];           // tf32-rounded W_proj

__device__ __forceinline__ float ftf32(float x) {
    float r;
    asm("cvt.rna.tf32.f32 %0, %1;" : "=f"(r) : "f"(x));
    return r;
}

__device__ __forceinline__ void mma_tf32(float* c, const uint32_t* a, const uint32_t* b) {
    asm volatile(
        "mma.sync.aligned.m16n8k8.row.col.f32.tf32.tf32.f32 "
        "{%0,%1,%2,%3}, {%4,%5,%6,%7}, {%8,%9}, {%0,%1,%2,%3};\n"
        : "+f"(c[0]), "+f"(c[1]), "+f"(c[2]), "+f"(c[3])
        : "r"(a[0]), "r"(a[1]), "r"(a[2]), "r"(a[3]), "r"(b[0]), "r"(b[1]));
}

__device__ __forceinline__ void cp16(uint32_t dst, const void* src) {
    asm volatile("cp.async.cg.shared.global [%0], [%1], 16;\n" :: "r"(dst), "l"(src));
}
__device__ __forceinline__ void cp_commit() {
    asm volatile("cp.async.commit_group;\n" ::: "memory");
}
__device__ __forceinline__ void cp_wait1() {
    asm volatile("cp.async.wait_group 1;\n" ::: "memory");
}

// ---------------------------------------------------------------------------
// Pre-round fp32 -> tf32 (vectorized grid-stride)
// ---------------------------------------------------------------------------
__global__ void round_kernel(const float4* __restrict__ src, float4* __restrict__ dst,
                             int n4) {
    int i = blockIdx.x * blockDim.x + threadIdx.x;
    int stride = gridDim.x * blockDim.x;
    for (; i < n4; i += stride) {
        float4 v = src[i];
        v.x = ftf32(v.x); v.y = ftf32(v.y); v.z = ftf32(v.z); v.w = ftf32(v.w);
        dst[i] = v;
    }
}

// ---------------------------------------------------------------------------
// TF32 tensor-core GEMM: C[M,N] = A[M,1024] @ B[1024,N]  (A,B pre-rounded tf32)
// 128x128 tile, BK=32, 3-stage cp.async, 128 threads = 4 warps of 64x64.
// Per kc step per warp: 32 LDS for 32 MMAs (1.0 LDS/MMA).
// Dynamic smem: A[3][128][36] | B[3][32][136] (107520 B), 2 CTAs/SM.
// SCATTER=true (QKV): q/k tiles get RoPE fused in the epilogue (smem-staged,
// rotate pairs in place, coalesced scatter); v tiles scatter with tf32 round.
// ---------------------------------------------------------------------------
constexpr int GA_STG = 128 * 36;   // floats per A stage
constexpr int GB_STG = 32 * 136;   // floats per B stage
constexpr int G_BOFF = 3 * GA_STG; // B region offset (floats)
constexpr int GEMM_SMEM = (G_BOFF + 3 * GB_STG) * 4;  // 107520 B
constexpr int CST = 136;           // epilogue staging stride

template<int N, bool SCATTER>
__global__ __launch_bounds__(128) void gemm_tf32(const float* __restrict__ A,
                                                 const float* __restrict__ B,
                                                 float* __restrict__ C,
                                                 const int* __restrict__ indices) {
    extern __shared__ float smg[];
    const uint32_t smem_b = (uint32_t)__cvta_generic_to_shared(smg);
    const int bx = blockIdx.x, by = blockIdx.y;
    const int tid = threadIdx.x;
    const int w = tid >> 5, lane = tid & 31;
    const int qr = lane >> 2, qc = lane & 3;
    const int wm = (w >> 1) * 64, wn = (w & 1) * 64;
    const float* Ap = A + (size_t)(by * 128) * 1024;
    const float* Bp = B + bx * 128;

    // A tile: [m][k] stride 36 (==4 mod 32); B tile: [k][n] stride 136 (==8 mod 32)
    auto issue = [&](int kt, int st) {
        const int k0 = kt * 32;
        uint32_t abase = smem_b + st * GA_STG * 4;
        uint32_t bbase = smem_b + (G_BOFF + st * GB_STG) * 4;
#pragma unroll
        for (int t = 0; t < 8; t++) {
            int idx = tid + t * 128;                          // 0..1023
            int r = idx >> 3, c4 = (idx & 7) * 4;             // A: 128 x 32
            cp16(abase + (r * 36 + c4) * 4, Ap + (size_t)r * 1024 + k0 + c4);
            int rb = idx >> 5, cb = (idx & 31) * 4;           // B: 32 x 128
            cp16(bbase + (rb * 136 + cb) * 4, Bp + (size_t)(k0 + rb) * N + cb);
        }
        cp_commit();
    };

    float acc[4][8][4];
#pragma unroll
    for (int i = 0; i < 4; i++)
#pragma unroll
        for (int j = 0; j < 8; j++)
#pragma unroll
            for (int u = 0; u < 4; u++) acc[i][j][u] = 0.0f;

    issue(0, 0); issue(1, 1);

    for (int kt = 0; kt < 32; kt++) {
        const int st = kt % 3;
        cp_wait1();          // stage kt landed
        __syncthreads();     // publish + all readers of stage (kt-1) done
        if (kt + 2 < 32) issue(kt + 2, (kt + 2) % 3);
        const float* As = smg + st * GA_STG;
        const float* Bs = smg + G_BOFF + st * GB_STG;
#pragma unroll
        for (int kc = 0; kc < 32; kc += 8) {
            uint32_t af[4][4], bf[8][2];
#pragma unroll
            for (int i = 0; i < 4; i++) {
                const float* ar = As + (wm + i * 16 + qr) * 36 + kc + qc;
                af[i][0] = __float_as_uint(ar[0]);
                af[i][1] = __float_as_uint(ar[8 * 36]);
                af[i][2] = __float_as_uint(ar[4]);
                af[i][3] = __float_as_uint(ar[8 * 36 + 4]);
            }
#pragma unroll
            for (int j = 0; j < 8; j++) {
                bf[j][0] = __float_as_uint(Bs[(kc + qc) * 136 + wn + j * 8 + qr]);
                bf[j][1] = __float_as_uint(Bs[(kc + 4 + qc) * 136 + wn + j * 8 + qr]);
            }
#pragma unroll
            for (int i = 0; i < 4; i++)
#pragma unroll
                for (int j = 0; j < 8; j++) mma_tf32(acc[i][j], af[i], bf[j]);
        }
    }

    if (!SCATTER) {
        // plain epilogue (proj GEMM)
#pragma unroll
        for (int i = 0; i < 4; i++)
#pragma unroll
            for (int j = 0; j < 8; j++) {
                int r0 = by * 128 + wm + i * 16 + qr;
                int c0 = bx * 128 + wn + j * 8 + 2 * qc;
#pragma unroll
                for (int u = 0; u < 4; u++)
                    C[(size_t)(r0 + (u >> 1) * 8) * NC + c0 + (u & 1)] = acc[i][j][u];
            }
        return;
    }

    const int part = bx >> 3;   // 0=q, 1=k, 2=v (each part spans 8 bx tiles)
    if (part == 2) {
        // v: direct scatter with tf32 round
#pragma unroll
        for (int i = 0; i < 4; i++)
#pragma unroll
            for (int j = 0; j < 8; j++) {
                int r0 = by * 128 + wm + i * 16 + qr;
                int c0 = bx * 128 + wn + j * 8 + 2 * qc;
#pragma unroll
                for (int u = 0; u < 4; u++) {
                    int row = r0 + (u >> 1) * 8;
                    int col = c0 + (u & 1);
                    int b = row >> 11, t = row & 2047;
                    int c = col & 1023;
                    int h = c >> 6, d = c & 63;
                    g_v[(size_t)(((b * NH + h) * NT) + t) * ND + d] = ftf32(acc[i][j][u]);
                }
            }
        return;
    }

    // q/k: stage -> rope in place -> coalesced scatter
    float* Cs = smg;   // reuse pipeline smem; 128*136 floats = 69.6 KB < 107.5 KB
    __syncthreads();   // all warps done with pipeline smem
#pragma unroll
    for (int i = 0; i < 4; i++)
#pragma unroll
        for (int j = 0; j < 8; j++) {
            int rl0 = wm + i * 16 + qr;
            int cl0 = wn + j * 8 + 2 * qc;
#pragma unroll
            for (int u = 0; u < 4; u++)
                Cs[(rl0 + (u >> 1) * 8) * CST + cl0 + (u & 1)] = acc[i][j][u];
        }
    __syncthreads();

    // rope: pair (l, l+32) within each 64-wide head; i = lane, rows split by warp
    const float invf = expf(-9.210340371976184f * (float)lane * (1.0f / 32.0f));
    for (int it = 0; it < 32; it++) {
        int r = it * 4 + w;
        int grow = by * 128 + r;
        int pos = indices[(grow >> 11) * NT + (grow & 2047)];
        float ang = (float)pos * invf;
        float sv, cv;
        sincosf(ang, &sv, &cv);
#pragma unroll
        for (int hh = 0; hh < 2; hh++) {
            int base = r * CST + hh * 64 + lane;
            float x1 = Cs[base], x2 = Cs[base + 32];
            Cs[base]      = ftf32(x1 * cv - x2 * sv);
            Cs[base + 32] = ftf32(x1 * sv + x2 * cv);
        }
    }
    __syncthreads();

    float* dst = (part == 0) ? g_q : g_k;
#pragma unroll
    for (int t2 = 0; t2 < 32; t2++) {
        int idx = tid + t2 * 128;          // 0..4095 float4s
        int r = idx >> 5, c4 = (idx & 31) * 4;
        float4 v = *(float4*)&Cs[r * CST + c4];
        int grow = by * 128 + r;
        int b = grow >> 11, t = grow & 2047;
        int col = bx * 128 + c4;
        int c = col & 1023;
        int h = c >> 6, d = c & 63;
        *(float4*)&dst[(size_t)(((b * NH + h) * NT) + t) * ND + d] = v;
    }
}

// ---------------------------------------------------------------------------
// Flash attention, TF32 tensor cores (unchanged from R7).
// ---------------------------------------------------------------------------
constexpr int QSTR = 68;
constexpr int KSTR = 68;
constexpr int VSTR = 72;
constexpr int OFF_K = 128 * QSTR;                 // 8704
constexpr int OFF_V = OFF_K + 2 * 64 * KSTR;      // 17408
constexpr int OFF_I = OFF_V + 2 * 64 * VSTR;      // 26624
constexpr int SMEM_WORDS = OFF_I + 2 * 64;        // 26752 words = 107008 B

__global__ __launch_bounds__(128) void attn_kernel(const int* __restrict__ indices) {
    const int qt = (gridDim.x - 1) - blockIdx.x;   // heavy blocks first
    const int h = blockIdx.y;
    const int b = blockIdx.z;
    const int q0 = qt * 128;
    const int tid = threadIdx.x;
    const int w = tid >> 5, lane = tid & 31;
    const int qr = lane >> 2, qc = lane & 3;
    const int rw = w * 32;

    extern __shared__ float sm[];
    float* Qs = sm;
    const uint32_t smem_b = (uint32_t)__cvta_generic_to_shared(sm);

    const size_t head_base = (size_t)((b * NH + h) * NT) * ND;
    const float* kg_base = g_k + head_base;
    const float* vg_base = g_v + head_base;
    const int* idx_base = indices + b * NT;

    auto issue_tile = [&](int kt, int buf) {
        const float* kg = kg_base + (size_t)(kt * 64) * ND;
        const float* vg = vg_base + (size_t)(kt * 64) * ND;
        uint32_t kdst = smem_b + (OFF_K + buf * 64 * KSTR) * 4;
        uint32_t vdst = smem_b + (OFF_V + buf * 64 * VSTR) * 4;
#pragma unroll
        for (int t = 0; t < 8; t++) {
            int idx = tid + t * 128;
            int r = idx >> 4, c4 = (idx & 15) * 4;
            cp16(kdst + (r * KSTR + c4) * 4, kg + r * ND + c4);
            cp16(vdst + (r * VSTR + c4) * 4, vg + r * ND + c4);
        }
        if (tid < 16)
            cp16(smem_b + (OFF_I + buf * 64 + tid * 4) * 4, idx_base + kt * 64 + tid * 4);
    };

#pragma unroll
    for (int t = 0; t < 16; t++) {
        int idx = tid + t * 128;
        int r = idx >> 4, d4 = (idx & 15) * 4;
        *(float4*)&Qs[r * QSTR + d4] =
            *(const float4*)(g_q + head_base + (size_t)(q0 + r) * ND + d4);
    }
    int qi[4];
#pragma unroll
    for (int mi = 0; mi < 2; mi++) {
        qi[mi * 2 + 0] = idx_base[q0 + rw + mi * 16 + qr];
        qi[mi * 2 + 1] = idx_base[q0 + rw + mi * 16 + qr + 8];
    }

    float mrow[4], lrow[4];
#pragma unroll
    for (int u = 0; u < 4; u++) { mrow[u] = -INFINITY; lrow[u] = 0.0f; }
    float o[2][8][4];
#pragma unroll
    for (int mi = 0; mi < 2; mi++)
#pragma unroll
        for (int j = 0; j < 8; j++)
#pragma unroll
            for (int u = 0; u < 4; u++) o[mi][j][u] = 0.0f;

    const int ktmax = 2 * qt + 1;
    issue_tile(0, 0); cp_commit();
    issue_tile(1, 1); cp_commit();

    for (int kt = 0; kt <= ktmax; kt++) {
        const int buf = kt & 1;
        float* Ks = sm + OFF_K + buf * 64 * KSTR;
        float* Vs = sm + OFF_V + buf * 64 * VSTR;
        const int* kidx = (const int*)(sm + OFF_I + buf * 64);

        cp_wait1();
        __syncthreads();

        float s[2][8][4];
#pragma unroll
        for (int mi = 0; mi < 2; mi++)
#pragma unroll
            for (int j = 0; j < 8; j++)
#pragma unroll
                for (int u = 0; u < 4; u++) s[mi][j][u] = 0.0f;
#pragma unroll
        for (int kc = 0; kc < 8; kc++) {
            uint32_t af[2][4];
#pragma unroll
            for (int mi = 0; mi < 2; mi++) {
                int r0 = (rw + mi * 16 + qr) * QSTR + kc * 8 + qc;
                af[mi][0] = __float_as_uint(Qs[r0]);
                af[mi][1] = __float_as_uint(Qs[r0 + 8 * QSTR]);
                af[mi][2] = __float_as_uint(Qs[r0 + 4]);
                af[mi][3] = __float_as_uint(Qs[r0 + 8 * QSTR + 4]);
            }
#pragma unroll
            for (int j = 0; j < 8; j++) {
                uint32_t bf[2];
                bf[0] = __float_as_uint(Ks[(j * 8 + qr) * KSTR + kc * 8 + qc]);
                bf[1] = __float_as_uint(Ks[(j * 8 + qr) * KSTR + kc * 8 + qc + 4]);
                mma_tf32(s[0][j], af[0], bf);
                mma_tf32(s[1][j], af[1], bf);
            }
        }

#pragma unroll
        for (int mi = 0; mi < 2; mi++) {
#pragma unroll
            for (int j = 0; j < 8; j++) {
                int c0 = j * 8 + 2 * qc;
                int kd0 = kidx[c0], kd1 = kidx[c0 + 1];
                s[mi][j][0] = (kd0 > qi[mi * 2 + 0]) ? -INFINITY : s[mi][j][0] * 0.125f;
                s[mi][j][1] = (kd1 > qi[mi * 2 + 0]) ? -INFINITY : s[mi][j][1] * 0.125f;
                s[mi][j][2] = (kd0 > qi[mi * 2 + 1]) ? -INFINITY : s[mi][j][2] * 0.125f;
                s[mi][j][3] = (kd1 > qi[mi * 2 + 1]) ? -INFINITY : s[mi][j][3] * 0.125f;
            }
            float tm0 = -INFINITY, tm1 = -INFINITY;
#pragma unroll
            for (int j = 0; j < 8; j++) {
                tm0 = fmaxf(tm0, fmaxf(s[mi][j][0], s[mi][j][1]));
                tm1 = fmaxf(tm1, fmaxf(s[mi][j][2], s[mi][j][3]));
            }
#pragma unroll
            for (int off = 1; off < 4; off <<= 1) {
                tm0 = fmaxf(tm0, __shfl_xor_sync(0xffffffffu, tm0, off));
                tm1 = fmaxf(tm1, __shfl_xor_sync(0xffffffffu, tm1, off));
            }
            float nm0 = fmaxf(mrow[mi * 2 + 0], tm0);
            float nm1 = fmaxf(mrow[mi * 2 + 1], tm1);
            float a0 = __expf(mrow[mi * 2 + 0] - nm0);
            float a1 = __expf(mrow[mi * 2 + 1] - nm1);
            mrow[mi * 2 + 0] = nm0; mrow[mi * 2 + 1] = nm1;
            float rs0 = 0.0f, rs1 = 0.0f;
#pragma unroll
            for (int j = 0; j < 8; j++) {
                s[mi][j][0] = ftf32(__expf(s[mi][j][0] - nm0));
                s[mi][j][1] = ftf32(__expf(s[mi][j][1] - nm0));
                s[mi][j][2] = ftf32(__expf(s[mi][j][2] - nm1));
                s[mi][j][3] = ftf32(__expf(s[mi][j][3] - nm1));
                rs0 += s[mi][j][0] + s[mi][j][1];
                rs1 += s[mi][j][2] + s[mi][j][3];
            }
#pragma unroll
            for (int off = 1; off < 4; off <<= 1) {
                rs0 += __shfl_xor_sync(0xffffffffu, rs0, off);
                rs1 += __shfl_xor_sync(0xffffffffu, rs1, off);
            }
            lrow[mi * 2 + 0] = lrow[mi * 2 + 0] * a0 + rs0;
            lrow[mi * 2 + 1] = lrow[mi * 2 + 1] * a1 + rs1;
#pragma unroll
            for (int j = 0; j < 8; j++) {
                o[mi][j][0] *= a0; o[mi][j][1] *= a0;
                o[mi][j][2] *= a1; o[mi][j][3] *= a1;
            }
        }

        const int src0 = (lane & ~3) | (qc >> 1);
        const int src1 = src0 + 2;
        const bool odd = (qc & 1);
#pragma unroll
        for (int kc = 0; kc < 8; kc++) {
            uint32_t af[2][4];
#pragma unroll
            for (int mi = 0; mi < 2; mi++) {
                float p0 = s[mi][kc][0], p1 = s[mi][kc][1];
                float p2 = s[mi][kc][2], p3 = s[mi][kc][3];
                float t00 = __shfl_sync(0xffffffffu, p0, src0);
                float t01 = __shfl_sync(0xffffffffu, p1, src0);
                float t10 = __shfl_sync(0xffffffffu, p0, src1);
                float t11 = __shfl_sync(0xffffffffu, p1, src1);
                float u00 = __shfl_sync(0xffffffffu, p2, src0);
                float u01 = __shfl_sync(0xffffffffu, p3, src0);
                float u10 = __shfl_sync(0xffffffffu, p2, src1);
                float u11 = __shfl_sync(0xffffffffu, p3, src1);
                af[mi][0] = __float_as_uint(odd ? t01 : t00);
                af[mi][1] = __float_as_uint(odd ? u01 : u00);
                af[mi][2] = __float_as_uint(odd ? t11 : t10);
                af[mi][3] = __float_as_uint(odd ? u11 : u10);
            }
#pragma unroll
            for (int j = 0; j < 8; j++) {
                uint32_t bf[2];
                bf[0] = __float_as_uint(Vs[(kc * 8 + qc) * VSTR + j * 8 + qr]);
                bf[1] = __float_as_uint(Vs[(kc * 8 + qc + 4) * VSTR + j * 8 + qr]);
                mma_tf32(o[0][j], af[0], bf);
                mma_tf32(o[1][j], af[1], bf);
            }
        }

        __syncthreads();
        if (kt + 2 <= ktmax) { issue_tile(kt + 2, buf); cp_commit(); }
    }

    // finalize: divide by l, tf32-round (proj GEMM consumes directly)
#pragma unroll
    for (int mi = 0; mi < 2; mi++) {
        float inv0 = 1.0f / lrow[mi * 2 + 0];
        float inv1 = 1.0f / lrow[mi * 2 + 1];
        size_t out0 = (size_t)(b * NT + q0 + rw + mi * 16 + qr) * NC + h * 64;
        size_t out1 = (size_t)(b * NT + q0 + rw + mi * 16 + qr + 8) * NC + h * 64;
#pragma unroll
        for (int j = 0; j < 8; j++) {
            int c0 = j * 8 + 2 * qc;
            float2 v0; v0.x = ftf32(o[mi][j][0] * inv0); v0.y = ftf32(o[mi][j][1] * inv0);
            float2 v1; v1.x = ftf32(o[mi][j][2] * inv1); v1.y = ftf32(o[mi][j][3] * inv1);
            *(float2*)&g_y[out0 + c0] = v0;
            *(float2*)&g_y[out1 + c0] = v1;
        }
    }
}

// ---------------------------------------------------------------------------
extern "C" void kernel_launch(void* const* d_in, const int* in_sizes, int n_in,
                              void* d_out, int out_size) {
    const float* x       = (const float*)d_in[0];
    const float* W_attn  = (const float*)d_in[1];
    const float* W_proj  = (const float*)d_in[2];
    const int*   indices = (const int*)d_in[3];
    float* out = (float*)d_out;

    static float *p_y = nullptr, *p_xr = nullptr, *p_war = nullptr, *p_wpr = nullptr;
    const int attn_smem = SMEM_WORDS * 4;   // 107008 B
    if (p_y == nullptr) {
        cudaFuncSetAttribute(attn_kernel, cudaFuncAttributeMaxDynamicSharedMemorySize,
                             attn_smem);
        cudaFuncSetAttribute(gemm_tf32<NQKV, true>,
                             cudaFuncAttributeMaxDynamicSharedMemorySize, GEMM_SMEM);
        cudaFuncSetAttribute(gemm_tf32<NC, false>,
                             cudaFuncAttributeMaxDynamicSharedMemorySize, GEMM_SMEM);
        void* p;
        cudaGetSymbolAddress(&p, g_y);   p_y   = (float*)p;
        cudaGetSymbolAddress(&p, g_xr);  p_xr  = (float*)p;
        cudaGetSymbolAddress(&p, g_war); p_war = (float*)p;
        cudaGetSymbolAddress(&p, g_wpr); p_wpr = (float*)p;
    }

    // pre-round inputs to tf32 (cp.async pipelines can't convert in flight)
    round_kernel<<<592, 256>>>((const float4*)x, (float4*)p_xr, NM * NC / 4);
    round_kernel<<<592, 256>>>((const float4*)W_attn, (float4*)p_war, NC * NQKV / 4);
    round_kernel<<<592, 256>>>((const float4*)W_proj, (float4*)p_wpr, NC * NC / 4);

    // QKV GEMM with fused RoPE epilogue (no separate rope kernel)
    gemm_tf32<NQKV, true><<<dim3(NQKV / 128, NM / 128), 128, GEMM_SMEM>>>(
        p_xr, p_war, nullptr, indices);

    attn_kernel<<<dim3(NT / 128, NH, NB), 128, attn_smem>>>(indices);

    gemm_tf32<NC, false><<<dim3(NC / 128, NM / 128), 128, GEMM_SMEM>>>(
        p_y, p_wpr, out, nullptr);
}